// round 4
// baseline (speedup 1.0000x reference)
#include <cuda_runtime.h>
#include <math.h>

// ---------------------------------------------------------------------------
// SindyLayer: replicate jax.experimental.ode.odeint (dopri5, rtol=atol=1e-3)
// for dy/dt = iAy split into (u,v): du/dt = -A v, dv/dt = A u, A sym 64x64.
// Output: u (real part) at t = 1..128, shape [4096, 128, 64] f32.
//
// One persistent launch; 128 blocks x 512 threads; 32 rows/block; state in
// SMEM. GLOBAL adaptive step controller (grid barrier + deterministic global
// reduction) -> every block follows JAX's exact step sequence. All controller
// arithmetic is bitwise-identical to the round-3 passing kernel (norm partials
// computed by tid<256 with the identical element mapping).
// ---------------------------------------------------------------------------

#define HID      64
#define RPB      32
#define NTH      512
#define NBLK     128
#define FORECAST 128
#define ARR      2048            // floats per (u or v) array per block
#define YSZ      4096            // u+v
#define APITCH   68
#define KSWAP    (6*YSZ)

// smem layout (floats)
#define OFF_A 0
#define OFF_Y (64*APITCH)              // two parity y buffers [u|v]
#define OFF_K (OFF_Y + 2*YSZ)          // k0..k6, each [u|v]
#define OFF_P (OFF_K + 7*YSZ)          // interp a,b,c,d,e (u only)
#define OFF_R (OFF_P + 5*ARR)          // reduction scratch
#define SM_FLOATS (OFF_R + 32)
#define SMEM_BYTES (SM_FLOATS*4)       // ~206 KB

typedef unsigned long long u64;

// ---- global controller state ----
__device__ float    g_red[2][2*NBLK];  // double-buffered partial sums
__device__ unsigned g_count;           // barrier counter (reset each launch)

// Dopri5 tableau exactly as in jax/experimental/ode.py
__constant__ float BETA[6][6] = {
  {(float)(1.0/5.0), 0.f, 0.f, 0.f, 0.f, 0.f},
  {(float)(3.0/40.0), (float)(9.0/40.0), 0.f, 0.f, 0.f, 0.f},
  {(float)(44.0/45.0), (float)(-56.0/15.0), (float)(32.0/9.0), 0.f, 0.f, 0.f},
  {(float)(19372.0/6561.0), (float)(-25360.0/2187.0), (float)(64448.0/6561.0),
   (float)(-212.0/729.0), 0.f, 0.f},
  {(float)(9017.0/3168.0), (float)(-355.0/33.0), (float)(46732.0/5247.0),
   (float)(49.0/176.0), (float)(-5103.0/18656.0), 0.f},
  {(float)(35.0/384.0), 0.f, (float)(500.0/1113.0), (float)(125.0/192.0),
   (float)(-2187.0/6784.0), (float)(11.0/84.0)}
};

// ---- packed f32x2 helpers (FFMA2 path) ----
__device__ __forceinline__ void ffma2(u64& d, u64 a, u64 b) {
  asm("fma.rn.f32x2 %0, %1, %2, %0;" : "+l"(d) : "l"(a), "l"(b));
}
__device__ __forceinline__ u64 ffma2o(u64 a, u64 b, u64 c) {
  u64 d;
  asm("fma.rn.f32x2 %0, %1, %2, %3;" : "=l"(d) : "l"(a), "l"(b), "l"(c));
  return d;
}
__device__ __forceinline__ u64 pack2(float x, float y) {
  u64 r; unsigned xi = __float_as_uint(x), yi = __float_as_uint(y);
  asm("mov.b64 %0, {%1, %2};" : "=l"(r) : "r"(xi), "r"(yi));
  return r;
}
__device__ __forceinline__ float2 unpack2(u64 v) {
  unsigned lo, hi;
  asm("mov.b64 {%0, %1}, %2;" : "=r"(lo), "=r"(hi) : "l"(v));
  return make_float2(__uint_as_float(lo), __uint_as_float(hi));
}

// Deterministic block-wide sum; result uniform across all threads.
// Warps 8..15 contribute +0.0f partials -> bitwise identical to the 256-thread
// version (adding +0 to a non-negative partial is an IEEE identity).
__device__ __forceinline__ float block_sum(float v, float* red) {
  __syncthreads();
  #pragma unroll
  for (int o = 16; o; o >>= 1) v += __shfl_down_sync(0xffffffffu, v, o);
  if ((threadIdx.x & 31) == 0) red[threadIdx.x >> 5] = v;
  __syncthreads();
  float s = red[0];
  #pragma unroll
  for (int w = 1; w < NTH/32; w++) s += red[w];
  return s;
}

// Grid barrier: monotonic counter; all 128 CTAs co-resident (1 CTA/SM).
__device__ __forceinline__ void gbar(unsigned& rnd) {
  __syncthreads();
  if (threadIdx.x == 0) {
    __threadfence();
    atomicAdd(&g_count, 1u);
    rnd += NBLK;
    volatile unsigned* vc = &g_count;
    while (*vc < rnd) __nanosleep(64);
    __threadfence();
  }
  __syncthreads();
}

// Global deterministic sum of up to two per-block values in one barrier round.
__device__ __forceinline__ void global_sum2(float v0, float v1, bool two,
                                            float* red, unsigned& rnd,
                                            int parity, float& s0, float& s1) {
  float b0 = block_sum(v0, red);
  float b1 = two ? block_sum(v1, red) : 0.f;
  if (threadIdx.x == 0) {
    g_red[parity][blockIdx.x] = b0;
    if (two) g_red[parity][NBLK + blockIdx.x] = b1;
  }
  gbar(rnd);
  float a0 = 0.f, a1 = 0.f;
  for (int b = 0; b < NBLK; b++) {
    a0 += __ldcg(&g_red[parity][b]);
    if (two) a1 += __ldcg(&g_red[parity][NBLK + b]);
  }
  s0 = a0; s1 = a1;
}

// RHS: k_u = -(v @ A^T), k_v = (u @ A^T). Thread owns column c, 4 rows.
// Per-(row,c) arithmetic identical to the 8-row version (same kp order).
__device__ __forceinline__ void rhs_eval(const float* __restrict__ y,
                                         float* __restrict__ kd,
                                         const u64* __restrict__ Areg,
                                         int c, int rbase)
{
  const float* yu = y;
  const float* yv = y + ARR;
  u64 aU[4], aV[4];
  #pragma unroll
  for (int i = 0; i < 4; i++) { aU[i] = 0ull; aV[i] = 0ull; }
  #pragma unroll
  for (int kp = 0; kp < 16; kp++) {
    u64 a0 = Areg[2*kp], a1 = Areg[2*kp+1];
    #pragma unroll
    for (int i = 0; i < 4; i++) {
      const int off = (rbase + i)*HID + kp*4;
      ulonglong2 v2 = *(const ulonglong2*)(yv + off);
      ulonglong2 u2 = *(const ulonglong2*)(yu + off);
      ffma2(aU[i], a0, v2.x); ffma2(aU[i], a1, v2.y);
      ffma2(aV[i], a0, u2.x); ffma2(aV[i], a1, u2.y);
    }
  }
  #pragma unroll
  for (int i = 0; i < 4; i++) {
    float2 su = unpack2(aU[i]);
    float2 sv = unpack2(aV[i]);
    kd[(rbase+i)*HID + c]       = -(su.x + su.y);
    kd[ARR + (rbase+i)*HID + c] =  (sv.x + sv.y);
  }
}

__global__ void reset_kernel() { g_count = 0u; }

__global__ void __launch_bounds__(NTH, 1)
sindy_kernel(const float* __restrict__ x,
             const float* __restrict__ tri,
             float* __restrict__ out)
{
  extern __shared__ float sm[];
  const int tid   = threadIdx.x;
  const int c     = tid & 63;
  const int rbase = (tid >> 6) * 4;     // 8 groups x 4 rows
  const int brow  = blockIdx.x * RPB;

  float* Asm = sm + OFF_A;
  float* K   = sm + OFF_K;
  float* P   = sm + OFF_P;
  float* RED = sm + OFF_R;

  unsigned rnd = 0;     // barrier round target
  int gp = 0;           // reduction buffer parity
  int k0o = 0;          // FSAL slot offset for k0 (0 or KSWAP)

  const float CE0 = (float)(35.0/384.0 - 1951.0/21600.0);
  const float CE2 = (float)(500.0/1113.0 - 22642.0/50085.0);
  const float CE3 = (float)(125.0/192.0 - 451.0/720.0);
  const float CE4 = (float)(-2187.0/6784.0 + 12231.0/42400.0);
  const float CE5 = (float)(11.0/84.0 - 649.0/6300.0);
  const float CE6 = (float)(-1.0/60.0);
  const float CM0 = (float)(6025192743.0/30085553152.0/2.0);
  const float CM2 = (float)(51252292925.0/65400821598.0/2.0);
  const float CM3 = (float)(-2691868925.0/45128329728.0/2.0);
  const float CM4 = (float)(187940372067.0/1594534317056.0/2.0);
  const float CM5 = (float)(-1776094331.0/19743644256.0/2.0);
  const float CM6 = (float)(11237099.0/235043384.0/2.0);

  // Build symmetric A from tril coefficients
  for (int idx = tid; idx < HID*HID; idx += NTH) {
    int r = idx >> 6, cc = idx & 63;
    int R = r > cc ? r : cc, C = r > cc ? cc : r;
    Asm[r*APITCH + cc] = tri[R*(R+1)/2 + C];
  }

  // y0 = (x, 0); emit output slice t=1 (== y0 per odeint semantics)
  {
    float* Y0 = sm + OFF_Y;
    int e4 = tid;                        // 512 float4 = ARR floats
    float4 xv = ((const float4*)x)[brow*16 + e4];
    ((float4*)Y0)[e4]         = xv;
    ((float4*)(Y0 + ARR))[e4] = make_float4(0.f, 0.f, 0.f, 0.f);
    int e = e4*4; int r = e >> 6; int h = e & 63;
    *(float4*)(out + ((size_t)(brow + r)*FORECAST + 0)*HID + h) = xv;
  }
  __syncthreads();

  // A row c -> registers as packed f32 pairs
  u64 Areg[32];
  #pragma unroll
  for (int i = 0; i < 32; i++)
    Areg[i] = *(const u64*)(Asm + c*APITCH + 2*i);

  int p = 0;
  float* ycur = sm + OFF_Y;
  float* yalt = sm + OFF_Y + YSZ;

  // f0 -> k0 (FSAL seed)
  rhs_eval(ycur, K, Areg, c, rbase);
  __syncthreads();

  // ---- initial_step_size (Hairer, order=4), GLOBAL norms ----
  float dt;
  {
    float s0 = 0.f, s1 = 0.f;
    if (tid < 256) {
      #pragma unroll
      for (int q = 0; q < 4; q++) {
        int e4 = tid + q*256;
        float4 y4 = ((const float4*)ycur)[e4];
        float4 f4 = ((const float4*)K)[e4];
        float ys[4] = {y4.x, y4.y, y4.z, y4.w};
        float fs[4] = {f4.x, f4.y, f4.z, f4.w};
        #pragma unroll
        for (int m = 0; m < 4; m++) {
          float sc = 1e-3f + 1e-3f*fabsf(ys[m]);
          float a0 = ys[m]/sc, a1 = fs[m]/sc;
          s0 = fmaf(a0, a0, s0); s1 = fmaf(a1, a1, s1);
        }
      }
    }
    float t0s, t1s;
    global_sum2(s0, s1, true, RED, rnd, gp, t0s, t1s); gp ^= 1;
    float d0 = sqrtf(t0s);
    float d1 = sqrtf(t1s);
    float h0 = (d0 < 1e-5f || d1 < 1e-5f) ? 1e-6f : 0.01f*d0/d1;
    #pragma unroll
    for (int q = 0; q < 2; q++) {
      int e4 = tid + q*NTH;
      float4 y4 = ((const float4*)ycur)[e4];
      float4 f4 = ((const float4*)K)[e4];
      float4 r4;
      r4.x = fmaf(h0, f4.x, y4.x); r4.y = fmaf(h0, f4.y, y4.y);
      r4.z = fmaf(h0, f4.z, y4.z); r4.w = fmaf(h0, f4.w, y4.w);
      ((float4*)yalt)[e4] = r4;
    }
    __syncthreads();
    rhs_eval(yalt, K + YSZ, Areg, c, rbase);        // f1 probe
    __syncthreads();
    float s2 = 0.f;
    if (tid < 256) {
      #pragma unroll
      for (int q = 0; q < 4; q++) {
        int e4 = tid + q*256;
        float4 y4  = ((const float4*)ycur)[e4];
        float4 f0v = ((const float4*)K)[e4];
        float4 f1v = ((const float4*)(K + YSZ))[e4];
        float ys[4] = {y4.x, y4.y, y4.z, y4.w};
        float a0[4] = {f0v.x, f0v.y, f0v.z, f0v.w};
        float a1[4] = {f1v.x, f1v.y, f1v.z, f1v.w};
        #pragma unroll
        for (int m = 0; m < 4; m++) {
          float sc = 1e-3f + 1e-3f*fabsf(ys[m]);
          float d = (a1[m] - a0[m])/sc;
          s2 = fmaf(d, d, s2);
        }
      }
    }
    float t2s, dum;
    global_sum2(s2, 0.f, false, RED, rnd, gp, t2s, dum); gp ^= 1;
    float d2 = sqrtf(t2s) / h0;
    float h1;
    if (d1 <= 1e-15f && d2 <= 1e-15f) h1 = fmaxf(1e-6f, h0*1e-3f);
    else                              h1 = powf(0.01f/fmaxf(d1, d2), 0.2f);
    dt = fminf(100.f*h0, h1);
  }

  float t = 1.f, last_t = 1.f;

  // ---- main scan over output targets ----
  for (int tgt = 2; tgt <= FORECAST; tgt++) {
    float tf = (float)tgt;
    int guard = 0;
    while (t < tf && dt > 0.f && guard < 100000) {
      guard++;
      ycur = sm + OFF_Y + p*YSZ;
      yalt = sm + OFF_Y + (p^1)*YSZ;
      const int k6o = k0o ^ KSWAP;      // stage-6 output slot (future k0)
      u64 dt2 = pack2(dt, dt);

      // stages 1..6
      for (int s = 1; s <= 6; s++) {
        ulonglong2 acc[2];
        #pragma unroll
        for (int q = 0; q < 2; q++) { acc[q].x = 0ull; acc[q].y = 0ull; }
        for (int j = 0; j < s; j++) {
          float bj = BETA[s-1][j];
          u64 b2 = pack2(bj, bj);
          const float* Kj = K + (j == 0 ? k0o : j*YSZ);
          #pragma unroll
          for (int q = 0; q < 2; q++) {
            ulonglong2 k2 = ((const ulonglong2*)Kj)[tid + q*NTH];
            ffma2(acc[q].x, b2, k2.x);
            ffma2(acc[q].y, b2, k2.y);
          }
        }
        #pragma unroll
        for (int q = 0; q < 2; q++) {
          ulonglong2 y2 = ((const ulonglong2*)ycur)[tid + q*NTH];
          ulonglong2 r2;
          r2.x = ffma2o(dt2, acc[q].x, y2.x);
          r2.y = ffma2o(dt2, acc[q].y, y2.y);
          ((ulonglong2*)yalt)[tid + q*NTH] = r2;
        }
        __syncthreads();
        rhs_eval(yalt, K + (s == 6 ? k6o : s*YSZ), Areg, c, rbase);
        __syncthreads();
      }
      // yalt == y1 (FSAL)

      // error ratio partial (tid<256 with round-3 mapping: bitwise identical)
      float ss = 0.f;
      if (tid < 256) {
        #pragma unroll
        for (int q = 0; q < 4; q++) {
          int e4 = tid + q*256;
          float4 k0 = ((const float4*)(K + k0o))[e4];
          float4 k2 = ((const float4*)(K + 2*YSZ))[e4];
          float4 k3 = ((const float4*)(K + 3*YSZ))[e4];
          float4 k4 = ((const float4*)(K + 4*YSZ))[e4];
          float4 k5 = ((const float4*)(K + 5*YSZ))[e4];
          float4 k6 = ((const float4*)(K + k6o))[e4];
          float4 y0v = ((const float4*)ycur)[e4];
          float4 y1v = ((const float4*)yalt)[e4];
          #define ECOMP(W) { \
            float er_ = dt*(CE0*k0.W + CE2*k2.W + CE3*k3.W + CE4*k4.W + CE5*k5.W + CE6*k6.W); \
            float tol_ = 1e-3f + 1e-3f*fmaxf(fabsf(y0v.W), fabsf(y1v.W)); \
            float rr_ = er_/tol_; ss = fmaf(rr_, rr_, ss); }
          ECOMP(x) ECOMP(y) ECOMP(z) ECOMP(w)
          #undef ECOMP
        }
      }
      float tss, dum;
      global_sum2(ss, 0.f, false, RED, rnd, gp, tss, dum); gp ^= 1;
      float ratio  = sqrtf(tss * (1.f/524288.f));
      float er     = fmaxf(ratio, 1e-10f);
      float dfac   = (ratio < 1.f) ? 1.f : 0.2f;
      float factor = fminf(10.f, fmaxf(0.9f*powf(er, -0.2f), dfac));
      bool  accept = (ratio <= 1.f);

      if (accept) {
        // interpolation coefficients (u components only): 512 float4 = ARR
        {
          int e4 = tid;
          float4 k0 = ((const float4*)(K + k0o))[e4];
          float4 k2 = ((const float4*)(K + 2*YSZ))[e4];
          float4 k3 = ((const float4*)(K + 3*YSZ))[e4];
          float4 k4 = ((const float4*)(K + 4*YSZ))[e4];
          float4 k5 = ((const float4*)(K + 5*YSZ))[e4];
          float4 k6 = ((const float4*)(K + k6o))[e4];
          float4 y0v = ((const float4*)ycur)[e4];
          float4 y1v = ((const float4*)yalt)[e4];
          float4 A4, B4, C4, D4, E4;
          #define ICOMP(W) { \
            float ym = fmaf(dt, CM0*k0.W + CM2*k2.W + CM3*k3.W + CM4*k4.W + CM5*k5.W + CM6*k6.W, y0v.W); \
            float D0 = dt*k0.W, D1 = dt*k6.W; \
            A4.W = -2.f*D0 + 2.f*D1 -  8.f*y0v.W -  8.f*y1v.W + 16.f*ym; \
            B4.W =  5.f*D0 - 3.f*D1 + 18.f*y0v.W + 14.f*y1v.W - 32.f*ym; \
            C4.W = -4.f*D0 +     D1 - 11.f*y0v.W -  5.f*y1v.W + 16.f*ym; \
            D4.W = D0; E4.W = y0v.W; }
          ICOMP(x) ICOMP(y) ICOMP(z) ICOMP(w)
          #undef ICOMP
          ((float4*)(P))[e4]         = A4;
          ((float4*)(P +   ARR))[e4] = B4;
          ((float4*)(P + 2*ARR))[e4] = C4;
          ((float4*)(P + 3*ARR))[e4] = D4;
          ((float4*)(P + 4*ARR))[e4] = E4;
        }
        // FSAL: k0 <- k6 by slot swap (no copy)
        k0o ^= KSWAP;
        last_t = t; t = t + dt; p ^= 1;
      }
      dt = dt * factor;
      __syncthreads();
    }

    // evaluate interpolation polynomial at the target and store
    float xr = (tf - last_t) / (t - last_t);
    {
      int e4 = tid;
      float4 A4 = ((const float4*)P)[e4];
      float4 B4 = ((const float4*)(P +   ARR))[e4];
      float4 C4 = ((const float4*)(P + 2*ARR))[e4];
      float4 D4 = ((const float4*)(P + 3*ARR))[e4];
      float4 E4 = ((const float4*)(P + 4*ARR))[e4];
      float4 o;
      o.x = fmaf(fmaf(fmaf(fmaf(A4.x, xr, B4.x), xr, C4.x), xr, D4.x), xr, E4.x);
      o.y = fmaf(fmaf(fmaf(fmaf(A4.y, xr, B4.y), xr, C4.y), xr, D4.y), xr, E4.y);
      o.z = fmaf(fmaf(fmaf(fmaf(A4.z, xr, B4.z), xr, C4.z), xr, D4.z), xr, E4.z);
      o.w = fmaf(fmaf(fmaf(fmaf(A4.w, xr, B4.w), xr, C4.w), xr, D4.w), xr, E4.w);
      int e = e4*4; int r = e >> 6; int h = e & 63;
      *(float4*)(out + ((size_t)(brow + r)*FORECAST + (tgt - 1))*HID + h) = o;
    }
  }
}

extern "C" void kernel_launch(void* const* d_in, const int* in_sizes, int n_in,
                              void* d_out, int out_size) {
  (void)in_sizes; (void)n_in; (void)out_size;
  const float* x   = (const float*)d_in[0];
  const float* tri = (const float*)d_in[1];
  float* out = (float*)d_out;
  cudaFuncSetAttribute(sindy_kernel,
                       cudaFuncAttributeMaxDynamicSharedMemorySize, SMEM_BYTES);
  reset_kernel<<<1, 1>>>();
  sindy_kernel<<<NBLK, NTH, SMEM_BYTES>>>(x, tri, out);
}

// round 5
// speedup vs baseline: 1.3312x; 1.3312x over previous
#include <cuda_runtime.h>
#include <math.h>

// ---------------------------------------------------------------------------
// SindyLayer: replicate jax.experimental.ode.odeint (dopri5, rtol=atol=1e-3)
// for dy/dt = iAy split into (u,v): du/dt = -A v, dv/dt = A u, A sym 64x64.
// Output: u (real part) at t = 1..128, shape [4096, 128, 64] f32.
//
// One persistent launch; 128 blocks x 512 threads; 32 rows/block; state in
// SMEM. GLOBAL adaptive step controller (grid barrier + deterministic global
// reduction) -> every block follows JAX's exact step sequence. Controller
// arithmetic bitwise-identical to the round-3 passing kernel.
// A is read from a kp-major SMEM layout (conflict-free LDS.128) instead of a
// 64-register per-thread cache -> no spills at the 128-reg/thread cap.
// ---------------------------------------------------------------------------

#define HID      64
#define RPB      32
#define NTH      512
#define NBLK     128
#define FORECAST 128
#define ARR      2048            // floats per (u or v) array per block
#define YSZ      4096            // u+v
#define KSWAP    (6*YSZ)

// smem layout (floats)
#define OFF_A 0                        // kp-major A: 16*256 = 4096 floats
#define OFF_Y 4096                     // two parity y buffers [u|v]
#define OFF_K (OFF_Y + 2*YSZ)          // k0..k6, each [u|v]
#define OFF_P (OFF_K + 7*YSZ)          // interp a,b,c,d,e (u only)
#define OFF_R (OFF_P + 5*ARR)          // reduction scratch
#define SM_FLOATS (OFF_R + 32)
#define SMEM_BYTES (SM_FLOATS*4)       // ~184 KB

typedef unsigned long long u64;

// ---- global controller state ----
__device__ float    g_red[2][2*NBLK];  // double-buffered partial sums
__device__ unsigned g_count;           // barrier counter (reset each launch)

// Dopri5 tableau exactly as in jax/experimental/ode.py
__constant__ float BETA[6][6] = {
  {(float)(1.0/5.0), 0.f, 0.f, 0.f, 0.f, 0.f},
  {(float)(3.0/40.0), (float)(9.0/40.0), 0.f, 0.f, 0.f, 0.f},
  {(float)(44.0/45.0), (float)(-56.0/15.0), (float)(32.0/9.0), 0.f, 0.f, 0.f},
  {(float)(19372.0/6561.0), (float)(-25360.0/2187.0), (float)(64448.0/6561.0),
   (float)(-212.0/729.0), 0.f, 0.f},
  {(float)(9017.0/3168.0), (float)(-355.0/33.0), (float)(46732.0/5247.0),
   (float)(49.0/176.0), (float)(-5103.0/18656.0), 0.f},
  {(float)(35.0/384.0), 0.f, (float)(500.0/1113.0), (float)(125.0/192.0),
   (float)(-2187.0/6784.0), (float)(11.0/84.0)}
};

// ---- packed f32x2 helpers (FFMA2 path) ----
__device__ __forceinline__ void ffma2(u64& d, u64 a, u64 b) {
  asm("fma.rn.f32x2 %0, %1, %2, %0;" : "+l"(d) : "l"(a), "l"(b));
}
__device__ __forceinline__ u64 ffma2o(u64 a, u64 b, u64 c) {
  u64 d;
  asm("fma.rn.f32x2 %0, %1, %2, %3;" : "=l"(d) : "l"(a), "l"(b), "l"(c));
  return d;
}
__device__ __forceinline__ u64 pack2(float x, float y) {
  u64 r; unsigned xi = __float_as_uint(x), yi = __float_as_uint(y);
  asm("mov.b64 %0, {%1, %2};" : "=l"(r) : "r"(xi), "r"(yi));
  return r;
}
__device__ __forceinline__ float2 unpack2(u64 v) {
  unsigned lo, hi;
  asm("mov.b64 {%0, %1}, %2;" : "=r"(lo), "=r"(hi) : "l"(v));
  return make_float2(__uint_as_float(lo), __uint_as_float(hi));
}

// Deterministic block-wide sum; result uniform across all threads.
// Warps 8..15 contribute +0.0f partials -> bitwise identical to the 256-thread
// version (adding +0 to a non-negative partial is an IEEE identity).
__device__ __forceinline__ float block_sum(float v, float* red) {
  __syncthreads();
  #pragma unroll
  for (int o = 16; o; o >>= 1) v += __shfl_down_sync(0xffffffffu, v, o);
  if ((threadIdx.x & 31) == 0) red[threadIdx.x >> 5] = v;
  __syncthreads();
  float s = red[0];
  #pragma unroll
  for (int w = 1; w < NTH/32; w++) s += red[w];
  return s;
}

// Grid barrier: monotonic counter; all 128 CTAs co-resident (1 CTA/SM).
__device__ __forceinline__ void gbar(unsigned& rnd) {
  __syncthreads();
  if (threadIdx.x == 0) {
    __threadfence();
    atomicAdd(&g_count, 1u);
    rnd += NBLK;
    volatile unsigned* vc = &g_count;
    while (*vc < rnd) __nanosleep(64);
    __threadfence();
  }
  __syncthreads();
}

// Global deterministic sum of up to two per-block values in one barrier round.
__device__ __forceinline__ void global_sum2(float v0, float v1, bool two,
                                            float* red, unsigned& rnd,
                                            int parity, float& s0, float& s1) {
  float b0 = block_sum(v0, red);
  float b1 = two ? block_sum(v1, red) : 0.f;
  if (threadIdx.x == 0) {
    g_red[parity][blockIdx.x] = b0;
    if (two) g_red[parity][NBLK + blockIdx.x] = b1;
  }
  gbar(rnd);
  float a0 = 0.f, a1 = 0.f;
  for (int b = 0; b < NBLK; b++) {
    a0 += __ldcg(&g_red[parity][b]);
    if (two) a1 += __ldcg(&g_red[parity][NBLK + b]);
  }
  s0 = a0; s1 = a1;
}

// RHS: k_u = -(v @ A^T), k_v = (u @ A^T). Thread owns column c, 4 rows.
// A pairs read from kp-major SMEM (lane c -> 16B-consecutive: conflict-free).
// Per-(row,c) arithmetic identical to round 3 (same kp order, same values).
__device__ __forceinline__ void rhs_eval(const float* __restrict__ y,
                                         float* __restrict__ kd,
                                         const float* __restrict__ Akp,
                                         int c, int rbase)
{
  const float* yu = y;
  const float* yv = y + ARR;
  const ulonglong2* __restrict__ A2 = (const ulonglong2*)Akp;
  u64 aU[4], aV[4];
  #pragma unroll
  for (int i = 0; i < 4; i++) { aU[i] = 0ull; aV[i] = 0ull; }
  #pragma unroll
  for (int kp = 0; kp < 16; kp++) {
    ulonglong2 a = A2[kp*64 + c];      // (A[c][4kp..4kp+1], A[c][4kp+2..4kp+3])
    #pragma unroll
    for (int i = 0; i < 4; i++) {
      const int off = (rbase + i)*HID + kp*4;
      ulonglong2 v2 = *(const ulonglong2*)(yv + off);
      ulonglong2 u2 = *(const ulonglong2*)(yu + off);
      ffma2(aU[i], a.x, v2.x); ffma2(aU[i], a.y, v2.y);
      ffma2(aV[i], a.x, u2.x); ffma2(aV[i], a.y, u2.y);
    }
  }
  #pragma unroll
  for (int i = 0; i < 4; i++) {
    float2 su = unpack2(aU[i]);
    float2 sv = unpack2(aV[i]);
    kd[(rbase+i)*HID + c]       = -(su.x + su.y);
    kd[ARR + (rbase+i)*HID + c] =  (sv.x + sv.y);
  }
}

__global__ void reset_kernel() { g_count = 0u; }

__global__ void __launch_bounds__(NTH, 1)
sindy_kernel(const float* __restrict__ x,
             const float* __restrict__ tri,
             float* __restrict__ out)
{
  extern __shared__ float sm[];
  const int tid   = threadIdx.x;
  const int c     = tid & 63;
  const int rbase = (tid >> 6) * 4;     // 8 groups x 4 rows
  const int brow  = blockIdx.x * RPB;

  float* Akp = sm + OFF_A;
  float* K   = sm + OFF_K;
  float* P   = sm + OFF_P;
  float* RED = sm + OFF_R;

  unsigned rnd = 0;     // barrier round target
  int gp = 0;           // reduction buffer parity
  int k0o = 0;          // FSAL slot offset for k0 (0 or KSWAP)

  const float CE0 = (float)(35.0/384.0 - 1951.0/21600.0);
  const float CE2 = (float)(500.0/1113.0 - 22642.0/50085.0);
  const float CE3 = (float)(125.0/192.0 - 451.0/720.0);
  const float CE4 = (float)(-2187.0/6784.0 + 12231.0/42400.0);
  const float CE5 = (float)(11.0/84.0 - 649.0/6300.0);
  const float CE6 = (float)(-1.0/60.0);
  const float CM0 = (float)(6025192743.0/30085553152.0/2.0);
  const float CM2 = (float)(51252292925.0/65400821598.0/2.0);
  const float CM3 = (float)(-2691868925.0/45128329728.0/2.0);
  const float CM4 = (float)(187940372067.0/1594534317056.0/2.0);
  const float CM5 = (float)(-1776094331.0/19743644256.0/2.0);
  const float CM6 = (float)(11237099.0/235043384.0/2.0);

  // Build kp-major A from tril coefficients:
  // Akp[kp*256 + cc*4 + m] = A[cc][kp*4+m]
  for (int idx = tid; idx < HID*HID; idx += NTH) {
    int kp = idx >> 8, rem = idx & 255;
    int cc = rem >> 2, m = rem & 3;
    int k = kp*4 + m;
    int R = cc > k ? cc : k, C = cc > k ? k : cc;
    Akp[idx] = tri[R*(R+1)/2 + C];
  }

  // y0 = (x, 0); emit output slice t=1 (== y0 per odeint semantics)
  {
    float* Y0 = sm + OFF_Y;
    int e4 = tid;                        // 512 float4 = ARR floats
    float4 xv = ((const float4*)x)[brow*16 + e4];
    ((float4*)Y0)[e4]         = xv;
    ((float4*)(Y0 + ARR))[e4] = make_float4(0.f, 0.f, 0.f, 0.f);
    int e = e4*4; int r = e >> 6; int h = e & 63;
    *(float4*)(out + ((size_t)(brow + r)*FORECAST + 0)*HID + h) = xv;
  }
  __syncthreads();

  int p = 0;
  float* ycur = sm + OFF_Y;
  float* yalt = sm + OFF_Y + YSZ;

  // f0 -> k0 (FSAL seed)
  rhs_eval(ycur, K, Akp, c, rbase);
  __syncthreads();

  // ---- initial_step_size (Hairer, order=4), GLOBAL norms ----
  float dt;
  {
    float s0 = 0.f, s1 = 0.f;
    if (tid < 256) {
      #pragma unroll
      for (int q = 0; q < 4; q++) {
        int e4 = tid + q*256;
        float4 y4 = ((const float4*)ycur)[e4];
        float4 f4 = ((const float4*)K)[e4];
        float ys[4] = {y4.x, y4.y, y4.z, y4.w};
        float fs[4] = {f4.x, f4.y, f4.z, f4.w};
        #pragma unroll
        for (int m = 0; m < 4; m++) {
          float sc = 1e-3f + 1e-3f*fabsf(ys[m]);
          float a0 = ys[m]/sc, a1 = fs[m]/sc;
          s0 = fmaf(a0, a0, s0); s1 = fmaf(a1, a1, s1);
        }
      }
    }
    float t0s, t1s;
    global_sum2(s0, s1, true, RED, rnd, gp, t0s, t1s); gp ^= 1;
    float d0 = sqrtf(t0s);
    float d1 = sqrtf(t1s);
    float h0 = (d0 < 1e-5f || d1 < 1e-5f) ? 1e-6f : 0.01f*d0/d1;
    #pragma unroll
    for (int q = 0; q < 2; q++) {
      int e4 = tid + q*NTH;
      float4 y4 = ((const float4*)ycur)[e4];
      float4 f4 = ((const float4*)K)[e4];
      float4 r4;
      r4.x = fmaf(h0, f4.x, y4.x); r4.y = fmaf(h0, f4.y, y4.y);
      r4.z = fmaf(h0, f4.z, y4.z); r4.w = fmaf(h0, f4.w, y4.w);
      ((float4*)yalt)[e4] = r4;
    }
    __syncthreads();
    rhs_eval(yalt, K + YSZ, Akp, c, rbase);        // f1 probe
    __syncthreads();
    float s2 = 0.f;
    if (tid < 256) {
      #pragma unroll
      for (int q = 0; q < 4; q++) {
        int e4 = tid + q*256;
        float4 y4  = ((const float4*)ycur)[e4];
        float4 f0v = ((const float4*)K)[e4];
        float4 f1v = ((const float4*)(K + YSZ))[e4];
        float ys[4] = {y4.x, y4.y, y4.z, y4.w};
        float a0[4] = {f0v.x, f0v.y, f0v.z, f0v.w};
        float a1[4] = {f1v.x, f1v.y, f1v.z, f1v.w};
        #pragma unroll
        for (int m = 0; m < 4; m++) {
          float sc = 1e-3f + 1e-3f*fabsf(ys[m]);
          float d = (a1[m] - a0[m])/sc;
          s2 = fmaf(d, d, s2);
        }
      }
    }
    float t2s, dum;
    global_sum2(s2, 0.f, false, RED, rnd, gp, t2s, dum); gp ^= 1;
    float d2 = sqrtf(t2s) / h0;
    float h1;
    if (d1 <= 1e-15f && d2 <= 1e-15f) h1 = fmaxf(1e-6f, h0*1e-3f);
    else                              h1 = powf(0.01f/fmaxf(d1, d2), 0.2f);
    dt = fminf(100.f*h0, h1);
  }

  float t = 1.f, last_t = 1.f;

  // ---- main scan over output targets ----
  for (int tgt = 2; tgt <= FORECAST; tgt++) {
    float tf = (float)tgt;
    int guard = 0;
    while (t < tf && dt > 0.f && guard < 100000) {
      guard++;
      ycur = sm + OFF_Y + p*YSZ;
      yalt = sm + OFF_Y + (p^1)*YSZ;
      const int k6o = k0o ^ KSWAP;      // stage-6 output slot (future k0)
      u64 dt2 = pack2(dt, dt);

      // stages 1..6
      for (int s = 1; s <= 6; s++) {
        ulonglong2 acc[2];
        #pragma unroll
        for (int q = 0; q < 2; q++) { acc[q].x = 0ull; acc[q].y = 0ull; }
        for (int j = 0; j < s; j++) {
          float bj = BETA[s-1][j];
          u64 b2 = pack2(bj, bj);
          const float* Kj = K + (j == 0 ? k0o : j*YSZ);
          #pragma unroll
          for (int q = 0; q < 2; q++) {
            ulonglong2 k2 = ((const ulonglong2*)Kj)[tid + q*NTH];
            ffma2(acc[q].x, b2, k2.x);
            ffma2(acc[q].y, b2, k2.y);
          }
        }
        #pragma unroll
        for (int q = 0; q < 2; q++) {
          ulonglong2 y2 = ((const ulonglong2*)ycur)[tid + q*NTH];
          ulonglong2 r2;
          r2.x = ffma2o(dt2, acc[q].x, y2.x);
          r2.y = ffma2o(dt2, acc[q].y, y2.y);
          ((ulonglong2*)yalt)[tid + q*NTH] = r2;
        }
        __syncthreads();
        rhs_eval(yalt, K + (s == 6 ? k6o : s*YSZ), Akp, c, rbase);
        __syncthreads();
      }
      // yalt == y1 (FSAL)

      // error ratio partial (tid<256 with round-3 mapping: bitwise identical)
      float ss = 0.f;
      if (tid < 256) {
        #pragma unroll
        for (int q = 0; q < 4; q++) {
          int e4 = tid + q*256;
          float4 k0 = ((const float4*)(K + k0o))[e4];
          float4 k2 = ((const float4*)(K + 2*YSZ))[e4];
          float4 k3 = ((const float4*)(K + 3*YSZ))[e4];
          float4 k4 = ((const float4*)(K + 4*YSZ))[e4];
          float4 k5 = ((const float4*)(K + 5*YSZ))[e4];
          float4 k6 = ((const float4*)(K + k6o))[e4];
          float4 y0v = ((const float4*)ycur)[e4];
          float4 y1v = ((const float4*)yalt)[e4];
          #define ECOMP(W) { \
            float er_ = dt*(CE0*k0.W + CE2*k2.W + CE3*k3.W + CE4*k4.W + CE5*k5.W + CE6*k6.W); \
            float tol_ = 1e-3f + 1e-3f*fmaxf(fabsf(y0v.W), fabsf(y1v.W)); \
            float rr_ = er_/tol_; ss = fmaf(rr_, rr_, ss); }
          ECOMP(x) ECOMP(y) ECOMP(z) ECOMP(w)
          #undef ECOMP
        }
      }
      float tss, dum;
      global_sum2(ss, 0.f, false, RED, rnd, gp, tss, dum); gp ^= 1;
      float ratio  = sqrtf(tss * (1.f/524288.f));
      float er     = fmaxf(ratio, 1e-10f);
      float dfac   = (ratio < 1.f) ? 1.f : 0.2f;
      float factor = fminf(10.f, fmaxf(0.9f*powf(er, -0.2f), dfac));
      bool  accept = (ratio <= 1.f);

      if (accept) {
        // interpolation coefficients (u components only): 512 float4 = ARR
        {
          int e4 = tid;
          float4 k0 = ((const float4*)(K + k0o))[e4];
          float4 k2 = ((const float4*)(K + 2*YSZ))[e4];
          float4 k3 = ((const float4*)(K + 3*YSZ))[e4];
          float4 k4 = ((const float4*)(K + 4*YSZ))[e4];
          float4 k5 = ((const float4*)(K + 5*YSZ))[e4];
          float4 k6 = ((const float4*)(K + k6o))[e4];
          float4 y0v = ((const float4*)ycur)[e4];
          float4 y1v = ((const float4*)yalt)[e4];
          float4 A4, B4, C4, D4, E4;
          #define ICOMP(W) { \
            float ym = fmaf(dt, CM0*k0.W + CM2*k2.W + CM3*k3.W + CM4*k4.W + CM5*k5.W + CM6*k6.W, y0v.W); \
            float D0 = dt*k0.W, D1 = dt*k6.W; \
            A4.W = -2.f*D0 + 2.f*D1 -  8.f*y0v.W -  8.f*y1v.W + 16.f*ym; \
            B4.W =  5.f*D0 - 3.f*D1 + 18.f*y0v.W + 14.f*y1v.W - 32.f*ym; \
            C4.W = -4.f*D0 +     D1 - 11.f*y0v.W -  5.f*y1v.W + 16.f*ym; \
            D4.W = D0; E4.W = y0v.W; }
          ICOMP(x) ICOMP(y) ICOMP(z) ICOMP(w)
          #undef ICOMP
          ((float4*)(P))[e4]         = A4;
          ((float4*)(P +   ARR))[e4] = B4;
          ((float4*)(P + 2*ARR))[e4] = C4;
          ((float4*)(P + 3*ARR))[e4] = D4;
          ((float4*)(P + 4*ARR))[e4] = E4;
        }
        // FSAL: k0 <- k6 by slot swap (no copy)
        k0o ^= KSWAP;
        last_t = t; t = t + dt; p ^= 1;
      }
      dt = dt * factor;
      __syncthreads();
    }

    // evaluate interpolation polynomial at the target and store
    float xr = (tf - last_t) / (t - last_t);
    {
      int e4 = tid;
      float4 A4 = ((const float4*)P)[e4];
      float4 B4 = ((const float4*)(P +   ARR))[e4];
      float4 C4 = ((const float4*)(P + 2*ARR))[e4];
      float4 D4 = ((const float4*)(P + 3*ARR))[e4];
      float4 E4 = ((const float4*)(P + 4*ARR))[e4];
      float4 o;
      o.x = fmaf(fmaf(fmaf(fmaf(A4.x, xr, B4.x), xr, C4.x), xr, D4.x), xr, E4.x);
      o.y = fmaf(fmaf(fmaf(fmaf(A4.y, xr, B4.y), xr, C4.y), xr, D4.y), xr, E4.y);
      o.z = fmaf(fmaf(fmaf(fmaf(A4.z, xr, B4.z), xr, C4.z), xr, D4.z), xr, E4.z);
      o.w = fmaf(fmaf(fmaf(fmaf(A4.w, xr, B4.w), xr, C4.w), xr, D4.w), xr, E4.w);
      int e = e4*4; int r = e >> 6; int h = e & 63;
      *(float4*)(out + ((size_t)(brow + r)*FORECAST + (tgt - 1))*HID + h) = o;
    }
  }
}

extern "C" void kernel_launch(void* const* d_in, const int* in_sizes, int n_in,
                              void* d_out, int out_size) {
  (void)in_sizes; (void)n_in; (void)out_size;
  const float* x   = (const float*)d_in[0];
  const float* tri = (const float*)d_in[1];
  float* out = (float*)d_out;
  cudaFuncSetAttribute(sindy_kernel,
                       cudaFuncAttributeMaxDynamicSharedMemorySize, SMEM_BYTES);
  reset_kernel<<<1, 1>>>();
  sindy_kernel<<<NBLK, NTH, SMEM_BYTES>>>(x, tri, out);
}

// round 8
// speedup vs baseline: 4.6305x; 3.4786x over previous
#include <cuda_runtime.h>
#include <math.h>

// ---------------------------------------------------------------------------
// SindyLayer: replicate jax.experimental.ode.odeint (dopri5, rtol=atol=1e-3)
// for dy/dt = iAy split into (u,v): du/dt = -A v, dv/dt = A u, A sym 64x64.
// Output: u (real part) at t = 1..128, shape [4096, 128, 64] f32.
//
// One persistent launch; 128 blocks x 256 threads; 32 rows/block; state in
// SMEM. GLOBAL adaptive step controller so every block follows JAX's exact
// step sequence. Cross-block reduction: per-slot release/acquire publication
// (payload __stcg -> __threadfence -> atomicExch(seq)), per-slot acquire
// spins, fixed-order 128-slot sum -> bitwise-identical, replay-deterministic.
//
// ROUND-8 FIX: the initial-step-size probe write covers the FULL y state
// (q<4 at NTH=256). Rounds 6/7 only wrote the u-half, leaving the v-half as
// stale SMEM -> deterministic first-call-vs-replay divergence.
// ---------------------------------------------------------------------------

#define HID      64
#define RPB      32
#define NTH      256
#define NBLK     128
#define FORECAST 128
#define ARR      2048            // floats per (u or v) array per block
#define YSZ      4096            // u+v
#define KSWAP    (6*YSZ)

// smem layout (floats)
#define OFF_A 0                        // kp-major A: 16*256 = 4096 floats
#define OFF_Y 4096                     // two parity y buffers [u|v]
#define OFF_K (OFF_Y + 2*YSZ)          // k0..k6, each [u|v]
#define OFF_P (OFF_K + 7*YSZ)          // interp a,b,c,d,e (u only)
#define OFF_R (OFF_P + 5*ARR)          // reduction scratch: 8 + 2*NBLK floats
#define SM_FLOATS (OFF_R + 8 + 2*NBLK + 8)
#define SMEM_BYTES (SM_FLOATS*4)

typedef unsigned long long u64;

// ---- global controller state (persistent; g_seq reset each launch) ----
__device__ float    g_val[2][2*NBLK];  // double-buffered payload (2 channels)
__device__ unsigned g_seq[NBLK];       // per-block monotonically increasing round id

// Dopri5 tableau exactly as in jax/experimental/ode.py
__constant__ float BETA[6][6] = {
  {(float)(1.0/5.0), 0.f, 0.f, 0.f, 0.f, 0.f},
  {(float)(3.0/40.0), (float)(9.0/40.0), 0.f, 0.f, 0.f, 0.f},
  {(float)(44.0/45.0), (float)(-56.0/15.0), (float)(32.0/9.0), 0.f, 0.f, 0.f},
  {(float)(19372.0/6561.0), (float)(-25360.0/2187.0), (float)(64448.0/6561.0),
   (float)(-212.0/729.0), 0.f, 0.f},
  {(float)(9017.0/3168.0), (float)(-355.0/33.0), (float)(46732.0/5247.0),
   (float)(49.0/176.0), (float)(-5103.0/18656.0), 0.f},
  {(float)(35.0/384.0), 0.f, (float)(500.0/1113.0), (float)(125.0/192.0),
   (float)(-2187.0/6784.0), (float)(11.0/84.0)}
};

// ---- packed f32x2 helpers (FFMA2 path) ----
__device__ __forceinline__ void ffma2(u64& d, u64 a, u64 b) {
  asm("fma.rn.f32x2 %0, %1, %2, %0;" : "+l"(d) : "l"(a), "l"(b));
}
__device__ __forceinline__ u64 ffma2o(u64 a, u64 b, u64 c) {
  u64 d;
  asm("fma.rn.f32x2 %0, %1, %2, %3;" : "=l"(d) : "l"(a), "l"(b), "l"(c));
  return d;
}
__device__ __forceinline__ u64 pack2(float x, float y) {
  u64 r; unsigned xi = __float_as_uint(x), yi = __float_as_uint(y);
  asm("mov.b64 %0, {%1, %2};" : "=l"(r) : "r"(xi), "r"(yi));
  return r;
}
__device__ __forceinline__ float2 unpack2(u64 v) {
  unsigned lo, hi;
  asm("mov.b64 {%0, %1}, %2;" : "=r"(lo), "=r"(hi) : "l"(v));
  return make_float2(__uint_as_float(lo), __uint_as_float(hi));
}

// Deterministic block-wide sum; result uniform across all 256 threads.
__device__ __forceinline__ float block_sum(float v, float* red) {
  __syncthreads();
  #pragma unroll
  for (int o = 16; o; o >>= 1) v += __shfl_down_sync(0xffffffffu, v, o);
  if ((threadIdx.x & 31) == 0) red[threadIdx.x >> 5] = v;
  __syncthreads();
  float s = red[0];
  #pragma unroll
  for (int w = 1; w < NTH/32; w++) s += red[w];
  return s;
}

__device__ __forceinline__ unsigned ld_seq_cg(const unsigned* p) {
  unsigned v;
  asm volatile("ld.global.cg.u32 %0, [%1];" : "=r"(v) : "l"(p));
  return v;
}

// Global deterministic sum of up to two per-block values.
// Release: payload __stcg -> __threadfence -> atomicExch(seq, rno).
// Acquire: per-slot spin on seq >= rno, fence, pull payload to SMEM,
// then every thread sums slots 0..127 in fixed order (bitwise-uniform).
// Doubles as a full grid barrier. rno must be uniform & increase by 1 per call.
__device__ __forceinline__ void global_sum2(float v0, float v1, bool two,
                                            float* red, unsigned rno,
                                            float& s0, float& s1) {
  const int par = rno & 1;
  float b0 = block_sum(v0, red);
  float b1 = two ? block_sum(v1, red) : 0.f;
  float* red2 = red + 8;
  if (threadIdx.x == 0) {
    __stcg(&g_val[par][blockIdx.x], b0);
    if (two) __stcg(&g_val[par][NBLK + blockIdx.x], b1);
    __threadfence();                       // release payload before flag
    atomicExch(&g_seq[blockIdx.x], rno);   // strong device-scope flag store
  }
  const int b = threadIdx.x;
  if (b < NBLK) {
    while (ld_seq_cg(&g_seq[b]) < rno) __nanosleep(32);
    __threadfence();                       // acquire: order payload read after flag
    red2[b] = __ldcg(&g_val[par][b]);
    if (two) red2[NBLK + b] = __ldcg(&g_val[par][NBLK + b]);
  }
  __syncthreads();
  float a0 = 0.f, a1 = 0.f;
  for (int i = 0; i < NBLK; i++) {
    a0 += red2[i];
    if (two) a1 += red2[NBLK + i];
  }
  s0 = a0; s1 = a1;
}

// RHS: k_u = -(v @ A^T), k_v = (u @ A^T). Thread owns 4 rows x 2 cols.
// Each broadcast y-load feeds both columns. Per-(row,col) even/odd-k packed
// accumulation order identical to round 3 -> bitwise identical k values.
__device__ __forceinline__ void rhs_eval(const float* __restrict__ y,
                                         float* __restrict__ kd,
                                         const float* __restrict__ Apk,
                                         int c0, int r0)
{
  const float* yu = y;
  const float* yv = y + ARR;
  const ulonglong2* __restrict__ A2 = (const ulonglong2*)Apk;
  u64 aU[4][2], aV[4][2];
  #pragma unroll
  for (int r = 0; r < 4; r++) {
    #pragma unroll
    for (int cc = 0; cc < 2; cc++) { aU[r][cc] = 0ull; aV[r][cc] = 0ull; }
  }
  #pragma unroll
  for (int kp = 0; kp < 16; kp++) {
    ulonglong2 A0 = A2[kp*64 + c0];
    ulonglong2 A1 = A2[kp*64 + c0 + 1];
    #pragma unroll
    for (int r = 0; r < 4; r++) {
      const int off = (r0 + r)*HID + kp*4;
      ulonglong2 v2 = *(const ulonglong2*)(yv + off);   // broadcast
      ulonglong2 u2 = *(const ulonglong2*)(yu + off);   // broadcast
      ffma2(aU[r][0], A0.x, v2.x); ffma2(aU[r][0], A0.y, v2.y);
      ffma2(aV[r][0], A0.x, u2.x); ffma2(aV[r][0], A0.y, u2.y);
      ffma2(aU[r][1], A1.x, v2.x); ffma2(aU[r][1], A1.y, v2.y);
      ffma2(aV[r][1], A1.x, u2.x); ffma2(aV[r][1], A1.y, u2.y);
    }
  }
  #pragma unroll
  for (int r = 0; r < 4; r++) {
    float2 su0 = unpack2(aU[r][0]), su1 = unpack2(aU[r][1]);
    float2 sv0 = unpack2(aV[r][0]), sv1 = unpack2(aV[r][1]);
    float2 ku = make_float2(-(su0.x + su0.y), -(su1.x + su1.y));
    float2 kv = make_float2( (sv0.x + sv0.y),  (sv1.x + sv1.y));
    *(float2*)(kd + (r0+r)*HID + c0)       = ku;
    *(float2*)(kd + ARR + (r0+r)*HID + c0) = kv;
  }
}

__global__ void reset_kernel() {
  if (threadIdx.x < NBLK) g_seq[threadIdx.x] = 0u;
}

__global__ void __launch_bounds__(NTH, 1)
sindy_kernel(const float* __restrict__ x,
             const float* __restrict__ tri,
             float* __restrict__ out)
{
  extern __shared__ float sm[];
  const int tid  = threadIdx.x;
  const int c0   = (tid & 31) * 2;      // 2 adjacent columns
  const int r0   = (tid >> 5) * 4;      // warp owns 4 rows (broadcast-friendly)
  const int brow = blockIdx.x * RPB;

  float* Apk = sm + OFF_A;
  float* K   = sm + OFF_K;
  float* P   = sm + OFF_P;
  float* RED = sm + OFF_R;

  unsigned rno = 1;     // reduction round id (uniform across grid)
  int k0o = 0;          // FSAL slot offset for k0 (0 or KSWAP)

  const float CE0 = (float)(35.0/384.0 - 1951.0/21600.0);
  const float CE2 = (float)(500.0/1113.0 - 22642.0/50085.0);
  const float CE3 = (float)(125.0/192.0 - 451.0/720.0);
  const float CE4 = (float)(-2187.0/6784.0 + 12231.0/42400.0);
  const float CE5 = (float)(11.0/84.0 - 649.0/6300.0);
  const float CE6 = (float)(-1.0/60.0);
  const float CM0 = (float)(6025192743.0/30085553152.0/2.0);
  const float CM2 = (float)(51252292925.0/65400821598.0/2.0);
  const float CM3 = (float)(-2691868925.0/45128329728.0/2.0);
  const float CM4 = (float)(187940372067.0/1594534317056.0/2.0);
  const float CM5 = (float)(-1776094331.0/19743644256.0/2.0);
  const float CM6 = (float)(11237099.0/235043384.0/2.0);

  // Build kp-major A: Apk[kp*256 + cc*4 + m] = A[cc][kp*4+m]
  for (int idx = tid; idx < HID*HID; idx += NTH) {
    int kp = idx >> 8, rem = idx & 255;
    int cc = rem >> 2, m = rem & 3;
    int k = kp*4 + m;
    int R = cc > k ? cc : k, C = cc > k ? k : cc;
    Apk[idx] = tri[R*(R+1)/2 + C];
  }

  // y0 = (x, 0); emit output slice t=1 (== y0 per odeint semantics)
  {
    float* Y0 = sm + OFF_Y;
    #pragma unroll
    for (int q = 0; q < 2; q++) {
      int e4 = tid + q*256;
      float4 xv = ((const float4*)x)[brow*16 + e4];
      ((float4*)Y0)[e4]         = xv;
      ((float4*)(Y0 + ARR))[e4] = make_float4(0.f, 0.f, 0.f, 0.f);
      int e = e4*4; int r = e >> 6; int h = e & 63;
      *(float4*)(out + ((size_t)(brow + r)*FORECAST + 0)*HID + h) = xv;
    }
  }
  __syncthreads();

  int p = 0;
  float* ycur = sm + OFF_Y;
  float* yalt = sm + OFF_Y + YSZ;

  // f0 -> k0 (FSAL seed)
  rhs_eval(ycur, K, Apk, c0, r0);
  __syncthreads();

  // ---- initial_step_size (Hairer, order=4), GLOBAL norms ----
  float dt;
  {
    float s0 = 0.f, s1 = 0.f;
    #pragma unroll
    for (int q = 0; q < 4; q++) {
      int e4 = tid + q*256;
      float4 y4 = ((const float4*)ycur)[e4];
      float4 f4 = ((const float4*)K)[e4];
      float ys[4] = {y4.x, y4.y, y4.z, y4.w};
      float fs[4] = {f4.x, f4.y, f4.z, f4.w};
      #pragma unroll
      for (int m = 0; m < 4; m++) {
        float sc = 1e-3f + 1e-3f*fabsf(ys[m]);
        float a0 = ys[m]/sc, a1 = fs[m]/sc;
        s0 = fmaf(a0, a0, s0); s1 = fmaf(a1, a1, s1);
      }
    }
    float t0s, t1s;
    global_sum2(s0, s1, true, RED, rno, t0s, t1s); rno++;
    float d0 = sqrtf(t0s);
    float d1 = sqrtf(t1s);
    float h0 = (d0 < 1e-5f || d1 < 1e-5f) ? 1e-6f : 0.01f*d0/d1;
    // ROUND-8 FIX: write the FULL probe state (u AND v halves): q<4 at NTH=256
    #pragma unroll
    for (int q = 0; q < 4; q++) {
      int e4 = tid + q*256;
      float4 y4 = ((const float4*)ycur)[e4];
      float4 f4 = ((const float4*)K)[e4];
      float4 r4;
      r4.x = fmaf(h0, f4.x, y4.x); r4.y = fmaf(h0, f4.y, y4.y);
      r4.z = fmaf(h0, f4.z, y4.z); r4.w = fmaf(h0, f4.w, y4.w);
      ((float4*)yalt)[e4] = r4;
    }
    __syncthreads();
    rhs_eval(yalt, K + YSZ, Apk, c0, r0);          // f1 probe
    __syncthreads();
    float s2 = 0.f;
    #pragma unroll
    for (int q = 0; q < 4; q++) {
      int e4 = tid + q*256;
      float4 y4  = ((const float4*)ycur)[e4];
      float4 f0v = ((const float4*)K)[e4];
      float4 f1v = ((const float4*)(K + YSZ))[e4];
      float ys[4] = {y4.x, y4.y, y4.z, y4.w};
      float a0[4] = {f0v.x, f0v.y, f0v.z, f0v.w};
      float a1[4] = {f1v.x, f1v.y, f1v.z, f1v.w};
      #pragma unroll
      for (int m = 0; m < 4; m++) {
        float sc = 1e-3f + 1e-3f*fabsf(ys[m]);
        float d = (a1[m] - a0[m])/sc;
        s2 = fmaf(d, d, s2);
      }
    }
    float t2s, dum;
    global_sum2(s2, 0.f, false, RED, rno, t2s, dum); rno++;
    float d2 = sqrtf(t2s) / h0;
    float h1;
    if (d1 <= 1e-15f && d2 <= 1e-15f) h1 = fmaxf(1e-6f, h0*1e-3f);
    else                              h1 = powf(0.01f/fmaxf(d1, d2), 0.2f);
    dt = fminf(100.f*h0, h1);
  }

  float t = 1.f, last_t = 1.f;

  // ---- main scan over output targets ----
  for (int tgt = 2; tgt <= FORECAST; tgt++) {
    float tf = (float)tgt;
    int guard = 0;
    while (t < tf && dt > 0.f && guard < 100000) {
      guard++;
      ycur = sm + OFF_Y + p*YSZ;
      yalt = sm + OFF_Y + (p^1)*YSZ;
      const int k6o = k0o ^ KSWAP;      // stage-6 output slot (future k0)
      u64 dt2 = pack2(dt, dt);

      // stages 1..6
      for (int s = 1; s <= 6; s++) {
        ulonglong2 acc[4];
        #pragma unroll
        for (int q = 0; q < 4; q++) { acc[q].x = 0ull; acc[q].y = 0ull; }
        for (int j = 0; j < s; j++) {
          float bj = BETA[s-1][j];
          u64 b2 = pack2(bj, bj);
          const float* Kj = K + (j == 0 ? k0o : j*YSZ);
          #pragma unroll
          for (int q = 0; q < 4; q++) {
            ulonglong2 k2 = ((const ulonglong2*)Kj)[tid + q*256];
            ffma2(acc[q].x, b2, k2.x);
            ffma2(acc[q].y, b2, k2.y);
          }
        }
        #pragma unroll
        for (int q = 0; q < 4; q++) {
          ulonglong2 y2 = ((const ulonglong2*)ycur)[tid + q*256];
          ulonglong2 r2;
          r2.x = ffma2o(dt2, acc[q].x, y2.x);
          r2.y = ffma2o(dt2, acc[q].y, y2.y);
          ((ulonglong2*)yalt)[tid + q*256] = r2;
        }
        __syncthreads();
        rhs_eval(yalt, K + (s == 6 ? k6o : s*YSZ), Apk, c0, r0);
        __syncthreads();
      }
      // yalt == y1 (FSAL)

      // error ratio partial (round-3 element mapping: bitwise identical)
      float ss = 0.f;
      #pragma unroll
      for (int q = 0; q < 4; q++) {
        int e4 = tid + q*256;
        float4 k0 = ((const float4*)(K + k0o))[e4];
        float4 k2 = ((const float4*)(K + 2*YSZ))[e4];
        float4 k3 = ((const float4*)(K + 3*YSZ))[e4];
        float4 k4 = ((const float4*)(K + 4*YSZ))[e4];
        float4 k5 = ((const float4*)(K + 5*YSZ))[e4];
        float4 k6 = ((const float4*)(K + k6o))[e4];
        float4 y0v = ((const float4*)ycur)[e4];
        float4 y1v = ((const float4*)yalt)[e4];
        #define ECOMP(W) { \
          float er_ = dt*(CE0*k0.W + CE2*k2.W + CE3*k3.W + CE4*k4.W + CE5*k5.W + CE6*k6.W); \
          float tol_ = 1e-3f + 1e-3f*fmaxf(fabsf(y0v.W), fabsf(y1v.W)); \
          float rr_ = er_/tol_; ss = fmaf(rr_, rr_, ss); }
        ECOMP(x) ECOMP(y) ECOMP(z) ECOMP(w)
        #undef ECOMP
      }
      float tss, dum;
      global_sum2(ss, 0.f, false, RED, rno, tss, dum); rno++;
      float ratio  = sqrtf(tss * (1.f/524288.f));
      float er     = fmaxf(ratio, 1e-10f);
      float dfac   = (ratio < 1.f) ? 1.f : 0.2f;
      float factor = fminf(10.f, fmaxf(0.9f*powf(er, -0.2f), dfac));
      bool  accept = (ratio <= 1.f);

      if (accept) {
        // interpolation coefficients (u components only)
        #pragma unroll
        for (int q = 0; q < 2; q++) {
          int e4 = tid + q*256;
          float4 k0 = ((const float4*)(K + k0o))[e4];
          float4 k2 = ((const float4*)(K + 2*YSZ))[e4];
          float4 k3 = ((const float4*)(K + 3*YSZ))[e4];
          float4 k4 = ((const float4*)(K + 4*YSZ))[e4];
          float4 k5 = ((const float4*)(K + 5*YSZ))[e4];
          float4 k6 = ((const float4*)(K + k6o))[e4];
          float4 y0v = ((const float4*)ycur)[e4];
          float4 y1v = ((const float4*)yalt)[e4];
          float4 A4, B4, C4, D4, E4;
          #define ICOMP(W) { \
            float ym = fmaf(dt, CM0*k0.W + CM2*k2.W + CM3*k3.W + CM4*k4.W + CM5*k5.W + CM6*k6.W, y0v.W); \
            float D0 = dt*k0.W, D1 = dt*k6.W; \
            A4.W = -2.f*D0 + 2.f*D1 -  8.f*y0v.W -  8.f*y1v.W + 16.f*ym; \
            B4.W =  5.f*D0 - 3.f*D1 + 18.f*y0v.W + 14.f*y1v.W - 32.f*ym; \
            C4.W = -4.f*D0 +     D1 - 11.f*y0v.W -  5.f*y1v.W + 16.f*ym; \
            D4.W = D0; E4.W = y0v.W; }
          ICOMP(x) ICOMP(y) ICOMP(z) ICOMP(w)
          #undef ICOMP
          ((float4*)(P))[e4]         = A4;
          ((float4*)(P +   ARR))[e4] = B4;
          ((float4*)(P + 2*ARR))[e4] = C4;
          ((float4*)(P + 3*ARR))[e4] = D4;
          ((float4*)(P + 4*ARR))[e4] = E4;
        }
        // FSAL: k0 <- k6 by slot swap (no copy)
        k0o ^= KSWAP;
        last_t = t; t = t + dt; p ^= 1;
      }
      dt = dt * factor;
      __syncthreads();
    }

    // evaluate interpolation polynomial at the target and store
    float xr = (tf - last_t) / (t - last_t);
    #pragma unroll
    for (int q = 0; q < 2; q++) {
      int e4 = tid + q*256;
      float4 A4 = ((const float4*)P)[e4];
      float4 B4 = ((const float4*)(P +   ARR))[e4];
      float4 C4 = ((const float4*)(P + 2*ARR))[e4];
      float4 D4 = ((const float4*)(P + 3*ARR))[e4];
      float4 E4 = ((const float4*)(P + 4*ARR))[e4];
      float4 o;
      o.x = fmaf(fmaf(fmaf(fmaf(A4.x, xr, B4.x), xr, C4.x), xr, D4.x), xr, E4.x);
      o.y = fmaf(fmaf(fmaf(fmaf(A4.y, xr, B4.y), xr, C4.y), xr, D4.y), xr, E4.y);
      o.z = fmaf(fmaf(fmaf(fmaf(A4.z, xr, B4.z), xr, C4.z), xr, D4.z), xr, E4.z);
      o.w = fmaf(fmaf(fmaf(fmaf(A4.w, xr, B4.w), xr, C4.w), xr, D4.w), xr, E4.w);
      int e = e4*4; int r = e >> 6; int h = e & 63;
      *(float4*)(out + ((size_t)(brow + r)*FORECAST + (tgt - 1))*HID + h) = o;
    }
  }
}

extern "C" void kernel_launch(void* const* d_in, const int* in_sizes, int n_in,
                              void* d_out, int out_size) {
  (void)in_sizes; (void)n_in; (void)out_size;
  const float* x   = (const float*)d_in[0];
  const float* tri = (const float*)d_in[1];
  float* out = (float*)d_out;
  cudaFuncSetAttribute(sindy_kernel,
                       cudaFuncAttributeMaxDynamicSharedMemorySize, SMEM_BYTES);
  reset_kernel<<<1, 128>>>();
  sindy_kernel<<<NBLK, NTH, SMEM_BYTES>>>(x, tri, out);
}

// round 10
// speedup vs baseline: 5.2213x; 1.1276x over previous
#include <cuda_runtime.h>
#include <math.h>

// ---------------------------------------------------------------------------
// SindyLayer: replicate jax.experimental.ode.odeint (dopri5, rtol=atol=1e-3)
// for dy/dt = iAy split into (u,v): du/dt = -A v, dv/dt = A u, A sym 64x64.
// Output: u (real part) at t = 1..128, shape [4096, 128, 64] f32.
//
// One persistent launch; 128 blocks x 256 threads; 32 rows/block; state in
// SMEM. GLOBAL adaptive step controller (per-slot release/acquire publication
// + fixed-order sum) -> bitwise-identical ratio in every block -> JAX's exact
// step sequence, replay-deterministic.
//
// ROUND-10: fix round-9 build break (BETAc must be __device__ constexpr to be
// referenced in device code without --expt-relaxed-constexpr). Design
// unchanged: k0..k3 and y register-resident; axpy/rhs share the same
// (4 rows x 2 cols) ownership; per-stage __syncthreads -> __syncwarp.
// ---------------------------------------------------------------------------

#define HID      64
#define RPB      32
#define NTH      256
#define NBLK     128
#define FORECAST 128
#define ARR      2048            // floats per (u or v) array per block
#define YSZ      4096            // u+v
#define KSWAP    (6*YSZ)

// smem layout (floats)
#define OFF_A 0                        // kp-major A: 16*256 = 4096 floats
#define OFF_Y 4096                     // two parity y buffers [u|v]
#define OFF_K (OFF_Y + 2*YSZ)          // k0..k6, each [u|v]
#define OFF_P (OFF_K + 7*YSZ)          // interp a,b,c,d,e (u only)
#define OFF_R (OFF_P + 5*ARR)          // reduction scratch: 8 + 2*NBLK floats
#define SM_FLOATS (OFF_R + 8 + 2*NBLK + 8)
#define SMEM_BYTES (SM_FLOATS*4)

typedef unsigned long long u64;

// ---- global controller state (persistent; g_seq reset each launch) ----
__device__ float    g_val[2][2*NBLK];  // double-buffered payload (2 channels)
__device__ unsigned g_seq[NBLK];       // per-block monotonically increasing round id

// Dopri5 tableau exactly as in jax/experimental/ode.py.
// __device__ constexpr: usable in device code; compile-time indices fold to
// FFMA immediates (no memory traffic).
__device__ constexpr float BETAc[6][6] = {
  {(float)(1.0/5.0), 0.f, 0.f, 0.f, 0.f, 0.f},
  {(float)(3.0/40.0), (float)(9.0/40.0), 0.f, 0.f, 0.f, 0.f},
  {(float)(44.0/45.0), (float)(-56.0/15.0), (float)(32.0/9.0), 0.f, 0.f, 0.f},
  {(float)(19372.0/6561.0), (float)(-25360.0/2187.0), (float)(64448.0/6561.0),
   (float)(-212.0/729.0), 0.f, 0.f},
  {(float)(9017.0/3168.0), (float)(-355.0/33.0), (float)(46732.0/5247.0),
   (float)(49.0/176.0), (float)(-5103.0/18656.0), 0.f},
  {(float)(35.0/384.0), 0.f, (float)(500.0/1113.0), (float)(125.0/192.0),
   (float)(-2187.0/6784.0), (float)(11.0/84.0)}
};

// ---- packed f32x2 helpers (FFMA2 path for rhs) ----
__device__ __forceinline__ void ffma2(u64& d, u64 a, u64 b) {
  asm("fma.rn.f32x2 %0, %1, %2, %0;" : "+l"(d) : "l"(a), "l"(b));
}
__device__ __forceinline__ float2 unpack2(u64 v) {
  unsigned lo, hi;
  asm("mov.b64 {%0, %1}, %2;" : "=r"(lo), "=r"(hi) : "l"(v));
  return make_float2(__uint_as_float(lo), __uint_as_float(hi));
}

// Deterministic block-wide sum; result uniform across all 256 threads.
__device__ __forceinline__ float block_sum(float v, float* red) {
  __syncthreads();
  #pragma unroll
  for (int o = 16; o; o >>= 1) v += __shfl_down_sync(0xffffffffu, v, o);
  if ((threadIdx.x & 31) == 0) red[threadIdx.x >> 5] = v;
  __syncthreads();
  float s = red[0];
  #pragma unroll
  for (int w = 1; w < NTH/32; w++) s += red[w];
  return s;
}

__device__ __forceinline__ unsigned ld_seq_cg(const unsigned* p) {
  unsigned v;
  asm volatile("ld.global.cg.u32 %0, [%1];" : "=r"(v) : "l"(p));
  return v;
}

// Global deterministic sum of up to two per-block values.
// Release: payload __stcg -> __threadfence -> atomicExch(seq, rno).
// Acquire: per-slot spin on seq >= rno, fence, pull payload to SMEM,
// then every thread sums slots 0..127 in fixed order (bitwise-uniform).
// Doubles as a full grid barrier. rno must be uniform & increase by 1 per call.
__device__ __forceinline__ void global_sum2(float v0, float v1, bool two,
                                            float* red, unsigned rno,
                                            float& s0, float& s1) {
  const int par = rno & 1;
  float b0 = block_sum(v0, red);
  float b1 = two ? block_sum(v1, red) : 0.f;
  float* red2 = red + 8;
  if (threadIdx.x == 0) {
    __stcg(&g_val[par][blockIdx.x], b0);
    if (two) __stcg(&g_val[par][NBLK + blockIdx.x], b1);
    __threadfence();                       // release payload before flag
    atomicExch(&g_seq[blockIdx.x], rno);   // strong device-scope flag store
  }
  const int b = threadIdx.x;
  if (b < NBLK) {
    while (ld_seq_cg(&g_seq[b]) < rno) __nanosleep(32);
    __threadfence();                       // acquire: order payload read after flag
    red2[b] = __ldcg(&g_val[par][b]);
    if (two) red2[NBLK + b] = __ldcg(&g_val[par][NBLK + b]);
  }
  __syncthreads();
  float a0 = 0.f, a1 = 0.f;
  for (int i = 0; i < NBLK; i++) {
    a0 += red2[i];
    if (two) a1 += red2[NBLK + i];
  }
  s0 = a0; s1 = a1;
}

// RHS: k_u = -(v @ A^T), k_v = (u @ A^T). Thread owns 4 rows x 2 cols.
// REGJ >= 0: also deposit results into kreg slot REGJ. TOSM: store to SMEM kd.
// Per-(row,col) even/odd-k packed accumulation order identical to round 3.
template<int REGJ, bool TOSM>
__device__ __forceinline__ void rhs_eval(const float* __restrict__ y,
                                         float* __restrict__ kd,
                                         const float* __restrict__ Apk,
                                         int c0, int r0,
                                         float (&kUr)[4][4][2],
                                         float (&kVr)[4][4][2])
{
  const float* yu = y;
  const float* yv = y + ARR;
  const ulonglong2* __restrict__ A2 = (const ulonglong2*)Apk;
  u64 aU[4][2], aV[4][2];
  #pragma unroll
  for (int r = 0; r < 4; r++) {
    #pragma unroll
    for (int cc = 0; cc < 2; cc++) { aU[r][cc] = 0ull; aV[r][cc] = 0ull; }
  }
  #pragma unroll 4
  for (int kp = 0; kp < 16; kp++) {
    ulonglong2 A0 = A2[kp*64 + c0];
    ulonglong2 A1 = A2[kp*64 + c0 + 1];
    #pragma unroll
    for (int r = 0; r < 4; r++) {
      const int off = (r0 + r)*HID + kp*4;
      ulonglong2 v2 = *(const ulonglong2*)(yv + off);   // broadcast
      ulonglong2 u2 = *(const ulonglong2*)(yu + off);   // broadcast
      ffma2(aU[r][0], A0.x, v2.x); ffma2(aU[r][0], A0.y, v2.y);
      ffma2(aV[r][0], A0.x, u2.x); ffma2(aV[r][0], A0.y, u2.y);
      ffma2(aU[r][1], A1.x, v2.x); ffma2(aU[r][1], A1.y, v2.y);
      ffma2(aV[r][1], A1.x, u2.x); ffma2(aV[r][1], A1.y, u2.y);
    }
  }
  #pragma unroll
  for (int r = 0; r < 4; r++) {
    float2 su0 = unpack2(aU[r][0]), su1 = unpack2(aU[r][1]);
    float2 sv0 = unpack2(aV[r][0]), sv1 = unpack2(aV[r][1]);
    float2 ku = make_float2(-(su0.x + su0.y), -(su1.x + su1.y));
    float2 kv = make_float2( (sv0.x + sv0.y),  (sv1.x + sv1.y));
    if (TOSM) {
      *(float2*)(kd + (r0+r)*HID + c0)       = ku;
      *(float2*)(kd + ARR + (r0+r)*HID + c0) = kv;
    }
    if (REGJ >= 0) {
      kUr[REGJ][r][0] = ku.x; kUr[REGJ][r][1] = ku.y;
      kVr[REGJ][r][0] = kv.x; kVr[REGJ][r][1] = kv.y;
    }
  }
}

__global__ void reset_kernel() {
  if (threadIdx.x < NBLK) g_seq[threadIdx.x] = 0u;
}

// Stage-state build: per-element fmaf chain identical to the packed version:
// acc=0; acc=fmaf(beta_j,k_j,acc) for j ascending; yi=fmaf(dt,acc,y).
#define AXPY_STAGE(S)                                                          \
  { _Pragma("unroll")                                                          \
    for (int r = 0; r < 4; r++) {                                              \
      float2 accu = make_float2(0.f, 0.f), accv = make_float2(0.f, 0.f);       \
      _Pragma("unroll")                                                        \
      for (int j = 0; j < ((S) < 4 ? (S) : 4); j++) {                          \
        float b = BETAc[(S)-1][j];                                             \
        accu.x = fmaf(b, kUr[j][r][0], accu.x);                                \
        accu.y = fmaf(b, kUr[j][r][1], accu.y);                                \
        accv.x = fmaf(b, kVr[j][r][0], accv.x);                                \
        accv.y = fmaf(b, kVr[j][r][1], accv.y);                                \
      }                                                                        \
      if ((S) >= 5) {                                                          \
        float b4 = BETAc[(S)-1][4];                                            \
        float2 k4u = *(const float2*)(K + 4*YSZ + (r0+r)*HID + c0);            \
        float2 k4v = *(const float2*)(K + 4*YSZ + ARR + (r0+r)*HID + c0);      \
        accu.x = fmaf(b4, k4u.x, accu.x); accu.y = fmaf(b4, k4u.y, accu.y);    \
        accv.x = fmaf(b4, k4v.x, accv.x); accv.y = fmaf(b4, k4v.y, accv.y);    \
      }                                                                        \
      if ((S) >= 6) {                                                          \
        float b5 = BETAc[(S)-1][5];                                            \
        float2 k5u = *(const float2*)(K + 5*YSZ + (r0+r)*HID + c0);            \
        float2 k5v = *(const float2*)(K + 5*YSZ + ARR + (r0+r)*HID + c0);      \
        accu.x = fmaf(b5, k5u.x, accu.x); accu.y = fmaf(b5, k5u.y, accu.y);    \
        accv.x = fmaf(b5, k5v.x, accv.x); accv.y = fmaf(b5, k5v.y, accv.y);    \
      }                                                                        \
      float2 ou, ov;                                                           \
      ou.x = fmaf(dt, accu.x, yUr[r][0]); ou.y = fmaf(dt, accu.y, yUr[r][1]);  \
      ov.x = fmaf(dt, accv.x, yVr[r][0]); ov.y = fmaf(dt, accv.y, yVr[r][1]);  \
      *(float2*)(yalt + (r0+r)*HID + c0)       = ou;                           \
      *(float2*)(yalt + ARR + (r0+r)*HID + c0) = ov;                           \
    } }

__global__ void __launch_bounds__(NTH, 1)
sindy_kernel(const float* __restrict__ x,
             const float* __restrict__ tri,
             float* __restrict__ out)
{
  extern __shared__ float sm[];
  const int tid  = threadIdx.x;
  const int c0   = (tid & 31) * 2;      // 2 adjacent columns
  const int r0   = (tid >> 5) * 4;      // warp owns 4 rows
  const int brow = blockIdx.x * RPB;

  float* Apk = sm + OFF_A;
  float* K   = sm + OFF_K;
  float* P   = sm + OFF_P;
  float* RED = sm + OFF_R;

  unsigned rno = 1;     // reduction round id (uniform across grid)
  int k0o = 0;          // FSAL slot offset for k0 (0 or KSWAP)

  // per-thread element registers (ownership: rows r0..r0+3, cols c0,c0+1)
  float yUr[4][2], yVr[4][2];
  float kUr[4][4][2], kVr[4][4][2];   // k0..k3

  const float CE0 = (float)(35.0/384.0 - 1951.0/21600.0);
  const float CE2 = (float)(500.0/1113.0 - 22642.0/50085.0);
  const float CE3 = (float)(125.0/192.0 - 451.0/720.0);
  const float CE4 = (float)(-2187.0/6784.0 + 12231.0/42400.0);
  const float CE5 = (float)(11.0/84.0 - 649.0/6300.0);
  const float CE6 = (float)(-1.0/60.0);
  const float CM0 = (float)(6025192743.0/30085553152.0/2.0);
  const float CM2 = (float)(51252292925.0/65400821598.0/2.0);
  const float CM3 = (float)(-2691868925.0/45128329728.0/2.0);
  const float CM4 = (float)(187940372067.0/1594534317056.0/2.0);
  const float CM5 = (float)(-1776094331.0/19743644256.0/2.0);
  const float CM6 = (float)(11237099.0/235043384.0/2.0);

  // Build kp-major A: Apk[kp*256 + cc*4 + m] = A[cc][kp*4+m]
  for (int idx = tid; idx < HID*HID; idx += NTH) {
    int kp = idx >> 8, rem = idx & 255;
    int cc = rem >> 2, m = rem & 3;
    int k = kp*4 + m;
    int R = cc > k ? cc : k, C = cc > k ? k : cc;
    Apk[idx] = tri[R*(R+1)/2 + C];
  }

  // y0 = (x, 0); emit output slice t=1 (== y0 per odeint semantics)
  {
    float* Y0 = sm + OFF_Y;
    #pragma unroll
    for (int q = 0; q < 2; q++) {
      int e4 = tid + q*256;
      float4 xv = ((const float4*)x)[brow*16 + e4];
      ((float4*)Y0)[e4]         = xv;
      ((float4*)(Y0 + ARR))[e4] = make_float4(0.f, 0.f, 0.f, 0.f);
      int e = e4*4; int r = e >> 6; int h = e & 63;
      *(float4*)(out + ((size_t)(brow + r)*FORECAST + 0)*HID + h) = xv;
    }
  }
  __syncthreads();

  int p = 0;
  float* ycur = sm + OFF_Y;
  float* yalt = sm + OFF_Y + YSZ;

  // f0 -> k0 (FSAL seed): registers + SMEM slot 0
  rhs_eval<0, true>(ycur, K, Apk, c0, r0, kUr, kVr);
  __syncthreads();

  // ---- initial_step_size (Hairer, order=4), GLOBAL norms ----
  float dt;
  {
    float s0 = 0.f, s1 = 0.f;
    #pragma unroll
    for (int q = 0; q < 4; q++) {
      int e4 = tid + q*256;
      float4 y4 = ((const float4*)ycur)[e4];
      float4 f4 = ((const float4*)K)[e4];
      float ys[4] = {y4.x, y4.y, y4.z, y4.w};
      float fs[4] = {f4.x, f4.y, f4.z, f4.w};
      #pragma unroll
      for (int m = 0; m < 4; m++) {
        float sc = 1e-3f + 1e-3f*fabsf(ys[m]);
        float a0 = ys[m]/sc, a1 = fs[m]/sc;
        s0 = fmaf(a0, a0, s0); s1 = fmaf(a1, a1, s1);
      }
    }
    float t0s, t1s;
    global_sum2(s0, s1, true, RED, rno, t0s, t1s); rno++;
    float d0 = sqrtf(t0s);
    float d1 = sqrtf(t1s);
    float h0 = (d0 < 1e-5f || d1 < 1e-5f) ? 1e-6f : 0.01f*d0/d1;
    // full probe state (u AND v halves)
    #pragma unroll
    for (int q = 0; q < 4; q++) {
      int e4 = tid + q*256;
      float4 y4 = ((const float4*)ycur)[e4];
      float4 f4 = ((const float4*)K)[e4];
      float4 r4;
      r4.x = fmaf(h0, f4.x, y4.x); r4.y = fmaf(h0, f4.y, y4.y);
      r4.z = fmaf(h0, f4.z, y4.z); r4.w = fmaf(h0, f4.w, y4.w);
      ((float4*)yalt)[e4] = r4;
    }
    __syncthreads();
    rhs_eval<-1, true>(yalt, K + YSZ, Apk, c0, r0, kUr, kVr);   // f1 probe
    __syncthreads();
    float s2 = 0.f;
    #pragma unroll
    for (int q = 0; q < 4; q++) {
      int e4 = tid + q*256;
      float4 y4  = ((const float4*)ycur)[e4];
      float4 f0v = ((const float4*)K)[e4];
      float4 f1v = ((const float4*)(K + YSZ))[e4];
      float ys[4] = {y4.x, y4.y, y4.z, y4.w};
      float a0[4] = {f0v.x, f0v.y, f0v.z, f0v.w};
      float a1[4] = {f1v.x, f1v.y, f1v.z, f1v.w};
      #pragma unroll
      for (int m = 0; m < 4; m++) {
        float sc = 1e-3f + 1e-3f*fabsf(ys[m]);
        float d = (a1[m] - a0[m])/sc;
        s2 = fmaf(d, d, s2);
      }
    }
    float t2s, dum;
    global_sum2(s2, 0.f, false, RED, rno, t2s, dum); rno++;
    float d2 = sqrtf(t2s) / h0;
    float h1;
    if (d1 <= 1e-15f && d2 <= 1e-15f) h1 = fmaxf(1e-6f, h0*1e-3f);
    else                              h1 = powf(0.01f/fmaxf(d1, d2), 0.2f);
    dt = fminf(100.f*h0, h1);
  }

  // load thread-own y elements into registers (ycur stable after barriers)
  #pragma unroll
  for (int r = 0; r < 4; r++) {
    float2 yu = *(const float2*)(ycur + (r0+r)*HID + c0);
    float2 yv = *(const float2*)(ycur + ARR + (r0+r)*HID + c0);
    yUr[r][0] = yu.x; yUr[r][1] = yu.y;
    yVr[r][0] = yv.x; yVr[r][1] = yv.y;
  }

  float t = 1.f, last_t = 1.f;

  // ---- main scan over output targets ----
  for (int tgt = 2; tgt <= FORECAST; tgt++) {
    float tf = (float)tgt;
    int guard = 0;
    while (t < tf && dt > 0.f && guard < 100000) {
      guard++;
      ycur = sm + OFF_Y + p*YSZ;
      yalt = sm + OFF_Y + (p^1)*YSZ;
      const int k6o = k0o ^ KSWAP;      // stage-6 output slot (future k0)

      // stages 1..6: register-resident stage combos + same-warp rhs
      AXPY_STAGE(1); __syncwarp();
      rhs_eval<1, false>(yalt, K, Apk, c0, r0, kUr, kVr); __syncwarp();
      AXPY_STAGE(2); __syncwarp();
      rhs_eval<2, true>(yalt, K + 2*YSZ, Apk, c0, r0, kUr, kVr); __syncwarp();
      AXPY_STAGE(3); __syncwarp();
      rhs_eval<3, true>(yalt, K + 3*YSZ, Apk, c0, r0, kUr, kVr); __syncwarp();
      AXPY_STAGE(4); __syncwarp();
      rhs_eval<-1, true>(yalt, K + 4*YSZ, Apk, c0, r0, kUr, kVr); __syncwarp();
      AXPY_STAGE(5); __syncwarp();
      rhs_eval<-1, true>(yalt, K + 5*YSZ, Apk, c0, r0, kUr, kVr); __syncwarp();
      AXPY_STAGE(6); __syncwarp();
      // k6 -> kreg slot 0 (FSAL) + SMEM k6o; on reject kreg0 is restored below
      rhs_eval<0, true>(yalt, K + k6o, Apk, c0, r0, kUr, kVr);
      __syncthreads();                  // k2..k6 + y1 visible to all warps
      // yalt == y1 (FSAL)

      // error ratio partial (round-3 element mapping: bitwise identical)
      float ss = 0.f;
      #pragma unroll
      for (int q = 0; q < 4; q++) {
        int e4 = tid + q*256;
        float4 k0 = ((const float4*)(K + k0o))[e4];
        float4 k2 = ((const float4*)(K + 2*YSZ))[e4];
        float4 k3 = ((const float4*)(K + 3*YSZ))[e4];
        float4 k4 = ((const float4*)(K + 4*YSZ))[e4];
        float4 k5 = ((const float4*)(K + 5*YSZ))[e4];
        float4 k6 = ((const float4*)(K + k6o))[e4];
        float4 y0v = ((const float4*)ycur)[e4];
        float4 y1v = ((const float4*)yalt)[e4];
        #define ECOMP(W) { \
          float er_ = dt*(CE0*k0.W + CE2*k2.W + CE3*k3.W + CE4*k4.W + CE5*k5.W + CE6*k6.W); \
          float tol_ = 1e-3f + 1e-3f*fmaxf(fabsf(y0v.W), fabsf(y1v.W)); \
          float rr_ = er_/tol_; ss = fmaf(rr_, rr_, ss); }
        ECOMP(x) ECOMP(y) ECOMP(z) ECOMP(w)
        #undef ECOMP
      }
      float tss, dum;
      global_sum2(ss, 0.f, false, RED, rno, tss, dum); rno++;
      float ratio  = sqrtf(tss * (1.f/524288.f));
      float er     = fmaxf(ratio, 1e-10f);
      float dfac   = (ratio < 1.f) ? 1.f : 0.2f;
      float factor = fminf(10.f, fmaxf(0.9f*powf(er, -0.2f), dfac));
      bool  accept = (ratio <= 1.f);

      if (accept) {
        // interpolation coefficients (u components only)
        #pragma unroll
        for (int q = 0; q < 2; q++) {
          int e4 = tid + q*256;
          float4 k0 = ((const float4*)(K + k0o))[e4];
          float4 k2 = ((const float4*)(K + 2*YSZ))[e4];
          float4 k3 = ((const float4*)(K + 3*YSZ))[e4];
          float4 k4 = ((const float4*)(K + 4*YSZ))[e4];
          float4 k5 = ((const float4*)(K + 5*YSZ))[e4];
          float4 k6 = ((const float4*)(K + k6o))[e4];
          float4 y0v = ((const float4*)ycur)[e4];
          float4 y1v = ((const float4*)yalt)[e4];
          float4 A4, B4, C4, D4, E4;
          #define ICOMP(W) { \
            float ym = fmaf(dt, CM0*k0.W + CM2*k2.W + CM3*k3.W + CM4*k4.W + CM5*k5.W + CM6*k6.W, y0v.W); \
            float D0 = dt*k0.W, D1 = dt*k6.W; \
            A4.W = -2.f*D0 + 2.f*D1 -  8.f*y0v.W -  8.f*y1v.W + 16.f*ym; \
            B4.W =  5.f*D0 - 3.f*D1 + 18.f*y0v.W + 14.f*y1v.W - 32.f*ym; \
            C4.W = -4.f*D0 +     D1 - 11.f*y0v.W -  5.f*y1v.W + 16.f*ym; \
            D4.W = D0; E4.W = y0v.W; }
          ICOMP(x) ICOMP(y) ICOMP(z) ICOMP(w)
          #undef ICOMP
          ((float4*)(P))[e4]         = A4;
          ((float4*)(P +   ARR))[e4] = B4;
          ((float4*)(P + 2*ARR))[e4] = C4;
          ((float4*)(P + 3*ARR))[e4] = D4;
          ((float4*)(P + 4*ARR))[e4] = E4;
        }
        // y-regs <- y1 (thread-own addresses; own stores -> no sync needed)
        #pragma unroll
        for (int r = 0; r < 4; r++) {
          float2 yu = *(const float2*)(yalt + (r0+r)*HID + c0);
          float2 yv = *(const float2*)(yalt + ARR + (r0+r)*HID + c0);
          yUr[r][0] = yu.x; yUr[r][1] = yu.y;
          yVr[r][0] = yv.x; yVr[r][1] = yv.y;
        }
        // FSAL: kreg0 already holds k6; swap SMEM slot
        k0o ^= KSWAP;
        last_t = t; t = t + dt; p ^= 1;
      } else {
        // reject: restore kreg0 from old k0 SMEM slot (thread-own addresses)
        #pragma unroll
        for (int r = 0; r < 4; r++) {
          float2 ku = *(const float2*)(K + k0o + (r0+r)*HID + c0);
          float2 kv = *(const float2*)(K + k0o + ARR + (r0+r)*HID + c0);
          kUr[0][r][0] = ku.x; kUr[0][r][1] = ku.y;
          kVr[0][r][0] = kv.x; kVr[0][r][1] = kv.y;
        }
      }
      dt = dt * factor;
      __syncthreads();   // protect yalt/ycur/P from next iteration's writes
    }

    // evaluate interpolation polynomial at the target and store
    float xr = (tf - last_t) / (t - last_t);
    #pragma unroll
    for (int q = 0; q < 2; q++) {
      int e4 = tid + q*256;
      float4 A4 = ((const float4*)P)[e4];
      float4 B4 = ((const float4*)(P +   ARR))[e4];
      float4 C4 = ((const float4*)(P + 2*ARR))[e4];
      float4 D4 = ((const float4*)(P + 3*ARR))[e4];
      float4 E4 = ((const float4*)(P + 4*ARR))[e4];
      float4 o;
      o.x = fmaf(fmaf(fmaf(fmaf(A4.x, xr, B4.x), xr, C4.x), xr, D4.x), xr, E4.x);
      o.y = fmaf(fmaf(fmaf(fmaf(A4.y, xr, B4.y), xr, C4.y), xr, D4.y), xr, E4.y);
      o.z = fmaf(fmaf(fmaf(fmaf(A4.z, xr, B4.z), xr, C4.z), xr, D4.z), xr, E4.z);
      o.w = fmaf(fmaf(fmaf(fmaf(A4.w, xr, B4.w), xr, C4.w), xr, D4.w), xr, E4.w);
      int e = e4*4; int r = e >> 6; int h = e & 63;
      *(float4*)(out + ((size_t)(brow + r)*FORECAST + (tgt - 1))*HID + h) = o;
    }
  }
}

extern "C" void kernel_launch(void* const* d_in, const int* in_sizes, int n_in,
                              void* d_out, int out_size) {
  (void)in_sizes; (void)n_in; (void)out_size;
  const float* x   = (const float*)d_in[0];
  const float* tri = (const float*)d_in[1];
  float* out = (float*)d_out;
  cudaFuncSetAttribute(sindy_kernel,
                       cudaFuncAttributeMaxDynamicSharedMemorySize, SMEM_BYTES);
  reset_kernel<<<1, 128>>>();
  sindy_kernel<<<NBLK, NTH, SMEM_BYTES>>>(x, tri, out);
}

// round 11
// speedup vs baseline: 5.4155x; 1.0372x over previous
#include <cuda_runtime.h>
#include <math.h>

// ---------------------------------------------------------------------------
// SindyLayer: replicate jax.experimental.ode.odeint (dopri5, rtol=atol=1e-3)
// for dy/dt = iAy split into (u,v): du/dt = -A v, dv/dt = A u, A sym 64x64.
// Output: u (real part) at t = 1..128, shape [4096, 128, 64] f32.
//
// ROUND-11: k0,k2,k3,k5,k6 fully register-resident (k1,k4 in 2 small SMEM
// slots, consumed thread-own). Error + interp passes computed from registers.
// Global reduction split publish/gather with speculative interp (double-
// buffered P) hiding the L2 round trip. Step sequence preserved (per-element
// arithmetic identical; only error-sum grouping changes, ~1e-7 ratio ulps).
// ---------------------------------------------------------------------------

#define HID      64
#define RPB      32
#define NTH      256
#define NBLK     128
#define FORECAST 128
#define ARR      2048            // floats per (u or v) array per block
#define YSZ      4096            // u+v

// smem layout (floats)
#define OFF_A 0                        // kp-major A: 16*256 = 4096 floats
#define OFF_Y 4096                     // two parity y buffers [u|v]
#define OFF_K (OFF_Y + 2*YSZ)          // 2 k slots: KS1, KS4 (init: f0, f1)
#define OFF_P (OFF_K + 2*YSZ)          // interp: 2 parity x 5 arrays (u only)
#define PH    (5*ARR)
#define OFF_R (OFF_P + 2*PH)           // reduction scratch
#define SM_FLOATS (OFF_R + 8 + 2*NBLK + 8)
#define SMEM_BYTES (SM_FLOATS*4)       // ~165 KB

typedef unsigned long long u64;

// ---- global controller state (persistent; g_seq reset each launch) ----
__device__ float    g_val[2][2*NBLK];  // double-buffered payload (2 channels)
__device__ unsigned g_seq[NBLK];       // per-block monotonically increasing round id

// Dopri5 tableau exactly as in jax/experimental/ode.py
__device__ constexpr float BETAc[6][6] = {
  {(float)(1.0/5.0), 0.f, 0.f, 0.f, 0.f, 0.f},
  {(float)(3.0/40.0), (float)(9.0/40.0), 0.f, 0.f, 0.f, 0.f},
  {(float)(44.0/45.0), (float)(-56.0/15.0), (float)(32.0/9.0), 0.f, 0.f, 0.f},
  {(float)(19372.0/6561.0), (float)(-25360.0/2187.0), (float)(64448.0/6561.0),
   (float)(-212.0/729.0), 0.f, 0.f},
  {(float)(9017.0/3168.0), (float)(-355.0/33.0), (float)(46732.0/5247.0),
   (float)(49.0/176.0), (float)(-5103.0/18656.0), 0.f},
  {(float)(35.0/384.0), 0.f, (float)(500.0/1113.0), (float)(125.0/192.0),
   (float)(-2187.0/6784.0), (float)(11.0/84.0)}
};

// ---- packed f32x2 helpers (FFMA2 path for rhs) ----
__device__ __forceinline__ void ffma2(u64& d, u64 a, u64 b) {
  asm("fma.rn.f32x2 %0, %1, %2, %0;" : "+l"(d) : "l"(a), "l"(b));
}
__device__ __forceinline__ float2 unpack2(u64 v) {
  unsigned lo, hi;
  asm("mov.b64 {%0, %1}, %2;" : "=r"(lo), "=r"(hi) : "l"(v));
  return make_float2(__uint_as_float(lo), __uint_as_float(hi));
}

// Deterministic block-wide sum; result uniform across all 256 threads.
__device__ __forceinline__ float block_sum(float v, float* red) {
  __syncthreads();
  #pragma unroll
  for (int o = 16; o; o >>= 1) v += __shfl_down_sync(0xffffffffu, v, o);
  if ((threadIdx.x & 31) == 0) red[threadIdx.x >> 5] = v;
  __syncthreads();
  float s = red[0];
  #pragma unroll
  for (int w = 1; w < NTH/32; w++) s += red[w];
  return s;
}

__device__ __forceinline__ unsigned ld_seq_cg(const unsigned* p) {
  unsigned v;
  asm volatile("ld.global.cg.u32 %0, [%1];" : "=r"(v) : "l"(p));
  return v;
}

// Release: payload __stcg -> __threadfence -> atomicExch(seq, rno).
__device__ __forceinline__ void gs_publish(float v, float* red, unsigned rno) {
  const int par = rno & 1;
  float b0 = block_sum(v, red);
  if (threadIdx.x == 0) {
    __stcg(&g_val[par][blockIdx.x], b0);
    __threadfence();
    atomicExch(&g_seq[blockIdx.x], rno);
  }
}
// Acquire: per-slot spin, fence, pull to SMEM, fixed-order sum (bitwise-uniform).
__device__ __forceinline__ float gs_gather(float* red, unsigned rno) {
  const int par = rno & 1;
  float* red2 = red + 8;
  const int b = threadIdx.x;
  if (b < NBLK) {
    while (ld_seq_cg(&g_seq[b]) < rno) __nanosleep(32);
    __threadfence();
    red2[b] = __ldcg(&g_val[par][b]);
  }
  __syncthreads();
  float a0 = 0.f;
  for (int i = 0; i < NBLK; i++) a0 += red2[i];
  return a0;
}

// Two-channel variant for init (publish+gather fused; doubles as grid barrier).
__device__ __forceinline__ void global_sum2(float v0, float v1, bool two,
                                            float* red, unsigned rno,
                                            float& s0, float& s1) {
  const int par = rno & 1;
  float b0 = block_sum(v0, red);
  float b1 = two ? block_sum(v1, red) : 0.f;
  float* red2 = red + 8;
  if (threadIdx.x == 0) {
    __stcg(&g_val[par][blockIdx.x], b0);
    if (two) __stcg(&g_val[par][NBLK + blockIdx.x], b1);
    __threadfence();
    atomicExch(&g_seq[blockIdx.x], rno);
  }
  const int b = threadIdx.x;
  if (b < NBLK) {
    while (ld_seq_cg(&g_seq[b]) < rno) __nanosleep(32);
    __threadfence();
    red2[b] = __ldcg(&g_val[par][b]);
    if (two) red2[NBLK + b] = __ldcg(&g_val[par][NBLK + b]);
  }
  __syncthreads();
  float a0 = 0.f, a1 = 0.f;
  for (int i = 0; i < NBLK; i++) {
    a0 += red2[i];
    if (two) a1 += red2[NBLK + i];
  }
  s0 = a0; s1 = a1;
}

// RHS: k_u = -(v @ A^T), k_v = (u @ A^T). Thread owns 4 rows x 2 cols.
// TOREG: deposit into register arrays; TOSM: store to SMEM slot kd.
// Per-(row,col) even/odd-k packed accumulation order identical to round 3.
template<bool TOREG, bool TOSM>
__device__ __forceinline__ void rhs_eval(const float* __restrict__ y,
                                         float* __restrict__ kd,
                                         const float* __restrict__ Apk,
                                         int c0, int r0,
                                         float (&oU)[4][2], float (&oV)[4][2])
{
  const float* yu = y;
  const float* yv = y + ARR;
  const ulonglong2* __restrict__ A2 = (const ulonglong2*)Apk;
  u64 aU[4][2], aV[4][2];
  #pragma unroll
  for (int r = 0; r < 4; r++) {
    #pragma unroll
    for (int cc = 0; cc < 2; cc++) { aU[r][cc] = 0ull; aV[r][cc] = 0ull; }
  }
  #pragma unroll 4
  for (int kp = 0; kp < 16; kp++) {
    ulonglong2 A0 = A2[kp*64 + c0];
    ulonglong2 A1 = A2[kp*64 + c0 + 1];
    #pragma unroll
    for (int r = 0; r < 4; r++) {
      const int off = (r0 + r)*HID + kp*4;
      ulonglong2 v2 = *(const ulonglong2*)(yv + off);   // broadcast
      ulonglong2 u2 = *(const ulonglong2*)(yu + off);   // broadcast
      ffma2(aU[r][0], A0.x, v2.x); ffma2(aU[r][0], A0.y, v2.y);
      ffma2(aV[r][0], A0.x, u2.x); ffma2(aV[r][0], A0.y, u2.y);
      ffma2(aU[r][1], A1.x, v2.x); ffma2(aU[r][1], A1.y, v2.y);
      ffma2(aV[r][1], A1.x, u2.x); ffma2(aV[r][1], A1.y, u2.y);
    }
  }
  #pragma unroll
  for (int r = 0; r < 4; r++) {
    float2 su0 = unpack2(aU[r][0]), su1 = unpack2(aU[r][1]);
    float2 sv0 = unpack2(aV[r][0]), sv1 = unpack2(aV[r][1]);
    float2 ku = make_float2(-(su0.x + su0.y), -(su1.x + su1.y));
    float2 kv = make_float2( (sv0.x + sv0.y),  (sv1.x + sv1.y));
    if (TOSM) {
      *(float2*)(kd + (r0+r)*HID + c0)       = ku;
      *(float2*)(kd + ARR + (r0+r)*HID + c0) = kv;
    }
    if (TOREG) {
      oU[r][0] = ku.x; oU[r][1] = ku.y;
      oV[r][0] = kv.x; oV[r][1] = kv.y;
    }
  }
}

__global__ void reset_kernel() {
  if (threadIdx.x < NBLK) g_seq[threadIdx.x] = 0u;
}

// Stage-state build helpers: per-element fmaf chain, j ascending, acc seed 0,
// final yi = fmaf(dt, acc, y). (Identical per-element ops as round 10.)
#define AXREG(B, KU, KV) { const float b_ = (B); \
  au.x = fmaf(b_, KU[r][0], au.x); au.y = fmaf(b_, KU[r][1], au.y); \
  av.x = fmaf(b_, KV[r][0], av.x); av.y = fmaf(b_, KV[r][1], av.y); }
#define AXSM(B, BASE) { const float b_ = (B); \
  float2 tu_ = *(const float2*)((BASE) + (r0+r)*HID + c0); \
  float2 tv_ = *(const float2*)((BASE) + ARR + (r0+r)*HID + c0); \
  au.x = fmaf(b_, tu_.x, au.x); au.y = fmaf(b_, tu_.y, au.y); \
  av.x = fmaf(b_, tv_.x, av.x); av.y = fmaf(b_, tv_.y, av.y); }
#define AXEND { float2 ou_, ov_; \
  ou_.x = fmaf(dt, au.x, yUr[r][0]); ou_.y = fmaf(dt, au.y, yUr[r][1]); \
  ov_.x = fmaf(dt, av.x, yVr[r][0]); ov_.y = fmaf(dt, av.y, yVr[r][1]); \
  *(float2*)(yalt + (r0+r)*HID + c0)       = ou_; \
  *(float2*)(yalt + ARR + (r0+r)*HID + c0) = ov_; }
#define AXBEGIN float2 au = make_float2(0.f,0.f), av = make_float2(0.f,0.f);

__global__ void __launch_bounds__(NTH, 1)
sindy_kernel(const float* __restrict__ x,
             const float* __restrict__ tri,
             float* __restrict__ out)
{
  extern __shared__ float sm[];
  const int tid  = threadIdx.x;
  const int c0   = (tid & 31) * 2;      // 2 adjacent columns
  const int r0   = (tid >> 5) * 4;      // warp owns 4 rows
  const int brow = blockIdx.x * RPB;

  float* Apk = sm + OFF_A;
  float* K   = sm + OFF_K;              // KS1 = K, KS4 = K + YSZ
  float* KS1 = K;
  float* KS4 = K + YSZ;
  float* Pb0 = sm + OFF_P;
  float* RED = sm + OFF_R;

  unsigned rno = 1;     // reduction round id (uniform across grid)
  int pp = 0;           // P parity (valid interp coefficients)

  // per-thread element registers (rows r0..r0+3, cols c0,c0+1)
  float yUr[4][2], yVr[4][2];
  float kU0[4][2], kV0[4][2];
  float kU2[4][2], kV2[4][2];
  float kU3[4][2], kV3[4][2];
  float kU5[4][2], kV5[4][2];
  float kU6[4][2], kV6[4][2];

  const float CE0 = (float)(35.0/384.0 - 1951.0/21600.0);
  const float CE2 = (float)(500.0/1113.0 - 22642.0/50085.0);
  const float CE3 = (float)(125.0/192.0 - 451.0/720.0);
  const float CE4 = (float)(-2187.0/6784.0 + 12231.0/42400.0);
  const float CE5 = (float)(11.0/84.0 - 649.0/6300.0);
  const float CE6 = (float)(-1.0/60.0);
  const float CM0 = (float)(6025192743.0/30085553152.0/2.0);
  const float CM2 = (float)(51252292925.0/65400821598.0/2.0);
  const float CM3 = (float)(-2691868925.0/45128329728.0/2.0);
  const float CM4 = (float)(187940372067.0/1594534317056.0/2.0);
  const float CM5 = (float)(-1776094331.0/19743644256.0/2.0);
  const float CM6 = (float)(11237099.0/235043384.0/2.0);

  // Build kp-major A: Apk[kp*256 + cc*4 + m] = A[cc][kp*4+m]
  for (int idx = tid; idx < HID*HID; idx += NTH) {
    int kp = idx >> 8, rem = idx & 255;
    int cc = rem >> 2, m = rem & 3;
    int k = kp*4 + m;
    int R = cc > k ? cc : k, C = cc > k ? k : cc;
    Apk[idx] = tri[R*(R+1)/2 + C];
  }

  // y0 = (x, 0); emit output slice t=1 (== y0 per odeint semantics)
  {
    float* Y0 = sm + OFF_Y;
    #pragma unroll
    for (int q = 0; q < 2; q++) {
      int e4 = tid + q*256;
      float4 xv = ((const float4*)x)[brow*16 + e4];
      ((float4*)Y0)[e4]         = xv;
      ((float4*)(Y0 + ARR))[e4] = make_float4(0.f, 0.f, 0.f, 0.f);
      int e = e4*4; int r = e >> 6; int h = e & 63;
      *(float4*)(out + ((size_t)(brow + r)*FORECAST + 0)*HID + h) = xv;
    }
  }
  __syncthreads();

  int p = 0;
  float* ycur = sm + OFF_Y;
  float* yalt = sm + OFF_Y + YSZ;

  // f0 -> k0 regs (FSAL seed) + SMEM slot KS1 for init norms
  rhs_eval<true, true>(ycur, K, Apk, c0, r0, kU0, kV0);
  __syncthreads();

  // ---- initial_step_size (Hairer, order=4), GLOBAL norms (unchanged) ----
  float dt;
  {
    float s0 = 0.f, s1 = 0.f;
    #pragma unroll
    for (int q = 0; q < 4; q++) {
      int e4 = tid + q*256;
      float4 y4 = ((const float4*)ycur)[e4];
      float4 f4 = ((const float4*)K)[e4];
      float ys[4] = {y4.x, y4.y, y4.z, y4.w};
      float fs[4] = {f4.x, f4.y, f4.z, f4.w};
      #pragma unroll
      for (int m = 0; m < 4; m++) {
        float sc = 1e-3f + 1e-3f*fabsf(ys[m]);
        float a0 = ys[m]/sc, a1 = fs[m]/sc;
        s0 = fmaf(a0, a0, s0); s1 = fmaf(a1, a1, s1);
      }
    }
    float t0s, t1s;
    global_sum2(s0, s1, true, RED, rno, t0s, t1s); rno++;
    float d0 = sqrtf(t0s);
    float d1 = sqrtf(t1s);
    float h0 = (d0 < 1e-5f || d1 < 1e-5f) ? 1e-6f : 0.01f*d0/d1;
    #pragma unroll
    for (int q = 0; q < 4; q++) {
      int e4 = tid + q*256;
      float4 y4 = ((const float4*)ycur)[e4];
      float4 f4 = ((const float4*)K)[e4];
      float4 r4;
      r4.x = fmaf(h0, f4.x, y4.x); r4.y = fmaf(h0, f4.y, y4.y);
      r4.z = fmaf(h0, f4.z, y4.z); r4.w = fmaf(h0, f4.w, y4.w);
      ((float4*)yalt)[e4] = r4;
    }
    __syncthreads();
    rhs_eval<false, true>(yalt, K + YSZ, Apk, c0, r0, kU0, kV0);  // f1 probe
    __syncthreads();
    float s2 = 0.f;
    #pragma unroll
    for (int q = 0; q < 4; q++) {
      int e4 = tid + q*256;
      float4 y4  = ((const float4*)ycur)[e4];
      float4 f0v = ((const float4*)K)[e4];
      float4 f1v = ((const float4*)(K + YSZ))[e4];
      float ys[4] = {y4.x, y4.y, y4.z, y4.w};
      float a0[4] = {f0v.x, f0v.y, f0v.z, f0v.w};
      float a1[4] = {f1v.x, f1v.y, f1v.z, f1v.w};
      #pragma unroll
      for (int m = 0; m < 4; m++) {
        float sc = 1e-3f + 1e-3f*fabsf(ys[m]);
        float d = (a1[m] - a0[m])/sc;
        s2 = fmaf(d, d, s2);
      }
    }
    float t2s, dum;
    global_sum2(s2, 0.f, false, RED, rno, t2s, dum); rno++;
    float d2 = sqrtf(t2s) / h0;
    float h1;
    if (d1 <= 1e-15f && d2 <= 1e-15f) h1 = fmaxf(1e-6f, h0*1e-3f);
    else                              h1 = powf(0.01f/fmaxf(d1, d2), 0.2f);
    dt = fminf(100.f*h0, h1);
  }

  // load thread-own y elements into registers
  #pragma unroll
  for (int r = 0; r < 4; r++) {
    float2 yu = *(const float2*)(ycur + (r0+r)*HID + c0);
    float2 yv = *(const float2*)(ycur + ARR + (r0+r)*HID + c0);
    yUr[r][0] = yu.x; yUr[r][1] = yu.y;
    yVr[r][0] = yv.x; yVr[r][1] = yv.y;
  }

  float t = 1.f, last_t = 1.f;

  // ---- main scan over output targets ----
  for (int tgt = 2; tgt <= FORECAST; tgt++) {
    float tf = (float)tgt;
    int guard = 0;
    while (t < tf && dt > 0.f && guard < 100000) {
      guard++;
      ycur = sm + OFF_Y + p*YSZ;
      yalt = sm + OFF_Y + (p^1)*YSZ;

      // ---- stages 1..6 (warp-local; k1,k4 via thread-own SMEM slots) ----
      // S1 -> k1 (SMEM)
      #pragma unroll
      for (int r = 0; r < 4; r++) { AXBEGIN AXREG(BETAc[0][0], kU0, kV0) AXEND }
      __syncwarp();
      rhs_eval<false, true>(yalt, KS1, Apk, c0, r0, kU0, kV0);
      __syncwarp();
      // S2 -> k2 (regs)
      #pragma unroll
      for (int r = 0; r < 4; r++) { AXBEGIN
        AXREG(BETAc[1][0], kU0, kV0) AXSM(BETAc[1][1], KS1) AXEND }
      __syncwarp();
      rhs_eval<true, false>(yalt, K, Apk, c0, r0, kU2, kV2);
      __syncwarp();
      // S3 -> k3 (regs)
      #pragma unroll
      for (int r = 0; r < 4; r++) { AXBEGIN
        AXREG(BETAc[2][0], kU0, kV0) AXSM(BETAc[2][1], KS1)
        AXREG(BETAc[2][2], kU2, kV2) AXEND }
      __syncwarp();
      rhs_eval<true, false>(yalt, K, Apk, c0, r0, kU3, kV3);
      __syncwarp();
      // S4 -> k4 (SMEM)
      #pragma unroll
      for (int r = 0; r < 4; r++) { AXBEGIN
        AXREG(BETAc[3][0], kU0, kV0) AXSM(BETAc[3][1], KS1)
        AXREG(BETAc[3][2], kU2, kV2) AXREG(BETAc[3][3], kU3, kV3) AXEND }
      __syncwarp();
      rhs_eval<false, true>(yalt, KS4, Apk, c0, r0, kU0, kV0);
      __syncwarp();
      // S5 -> k5 (regs)
      #pragma unroll
      for (int r = 0; r < 4; r++) { AXBEGIN
        AXREG(BETAc[4][0], kU0, kV0) AXSM(BETAc[4][1], KS1)
        AXREG(BETAc[4][2], kU2, kV2) AXREG(BETAc[4][3], kU3, kV3)
        AXSM(BETAc[4][4], KS4) AXEND }
      __syncwarp();
      rhs_eval<true, false>(yalt, K, Apk, c0, r0, kU5, kV5);
      __syncwarp();
      // S6 -> k6 (regs); beta[5][1] == 0 -> k1 term skipped
      #pragma unroll
      for (int r = 0; r < 4; r++) { AXBEGIN
        AXREG(BETAc[5][0], kU0, kV0)
        AXREG(BETAc[5][2], kU2, kV2) AXREG(BETAc[5][3], kU3, kV3)
        AXSM(BETAc[5][4], KS4) AXREG(BETAc[5][5], kU5, kV5) AXEND }
      __syncwarp();
      rhs_eval<true, false>(yalt, K, Apk, c0, r0, kU6, kV6);
      __syncwarp();
      // yalt == y1 (FSAL)

      // ---- error-ratio partial from registers + thread-own SMEM ----
      float ss = 0.f;
      #pragma unroll
      for (int r = 0; r < 4; r++) {
        float2 k4u = *(const float2*)(KS4 + (r0+r)*HID + c0);
        float2 k4v = *(const float2*)(KS4 + ARR + (r0+r)*HID + c0);
        float2 y1u = *(const float2*)(yalt + (r0+r)*HID + c0);
        float2 y1v = *(const float2*)(yalt + ARR + (r0+r)*HID + c0);
        #define EC(K0,K2,K3,K4,K5,K6,Y0,Y1) { \
          float er_ = dt*(CE0*(K0) + CE2*(K2) + CE3*(K3) + CE4*(K4) + CE5*(K5) + CE6*(K6)); \
          float tol_ = 1e-3f + 1e-3f*fmaxf(fabsf(Y0), fabsf(Y1)); \
          float rr_ = er_/tol_; ss = fmaf(rr_, rr_, ss); }
        EC(kU0[r][0],kU2[r][0],kU3[r][0],k4u.x,kU5[r][0],kU6[r][0],yUr[r][0],y1u.x)
        EC(kU0[r][1],kU2[r][1],kU3[r][1],k4u.y,kU5[r][1],kU6[r][1],yUr[r][1],y1u.y)
        EC(kV0[r][0],kV2[r][0],kV3[r][0],k4v.x,kV5[r][0],kV6[r][0],yVr[r][0],y1v.x)
        EC(kV0[r][1],kV2[r][1],kV3[r][1],k4v.y,kV5[r][1],kV6[r][1],yVr[r][1],y1v.y)
        #undef EC
      }
      gs_publish(ss, RED, rno);

      // ---- speculative interp coefficients (u only) into P[pp^1] ----
      {
        float* Pn = Pb0 + (pp^1)*PH;
        #pragma unroll
        for (int r = 0; r < 4; r++) {
          float2 k4u = *(const float2*)(KS4 + (r0+r)*HID + c0);
          float2 y1u = *(const float2*)(yalt + (r0+r)*HID + c0);
          float2 A2f, B2f, C2f, D2f, E2f;
          #define IC(W, K0,K2,K3,K4,K5,K6,Y0,Y1) { \
            float ym = fmaf(dt, CM0*(K0) + CM2*(K2) + CM3*(K3) + CM4*(K4) + CM5*(K5) + CM6*(K6), (Y0)); \
            float D0 = dt*(K0), D1 = dt*(K6); \
            A2f.W = -2.f*D0 + 2.f*D1 -  8.f*(Y0) -  8.f*(Y1) + 16.f*ym; \
            B2f.W =  5.f*D0 - 3.f*D1 + 18.f*(Y0) + 14.f*(Y1) - 32.f*ym; \
            C2f.W = -4.f*D0 +     D1 - 11.f*(Y0) -  5.f*(Y1) + 16.f*ym; \
            D2f.W = D0; E2f.W = (Y0); }
          IC(x, kU0[r][0],kU2[r][0],kU3[r][0],k4u.x,kU5[r][0],kU6[r][0],yUr[r][0],y1u.x)
          IC(y, kU0[r][1],kU2[r][1],kU3[r][1],k4u.y,kU5[r][1],kU6[r][1],yUr[r][1],y1u.y)
          #undef IC
          *(float2*)(Pn + 0*ARR + (r0+r)*HID + c0) = A2f;
          *(float2*)(Pn + 1*ARR + (r0+r)*HID + c0) = B2f;
          *(float2*)(Pn + 2*ARR + (r0+r)*HID + c0) = C2f;
          *(float2*)(Pn + 3*ARR + (r0+r)*HID + c0) = D2f;
          *(float2*)(Pn + 4*ARR + (r0+r)*HID + c0) = E2f;
        }
      }

      float tss = gs_gather(RED, rno); rno++;
      float ratio  = sqrtf(tss * (1.f/524288.f));
      float er     = fmaxf(ratio, 1e-10f);
      float dfac   = (ratio < 1.f) ? 1.f : 0.2f;
      float factor = fminf(10.f, fmaxf(0.9f*powf(er, -0.2f), dfac));
      bool  accept = (ratio <= 1.f);

      if (accept) {
        pp ^= 1;                         // speculative P becomes valid
        // FSAL: k0 <- k6 (register copies)
        #pragma unroll
        for (int r = 0; r < 4; r++) {
          kU0[r][0] = kU6[r][0]; kU0[r][1] = kU6[r][1];
          kV0[r][0] = kV6[r][0]; kV0[r][1] = kV6[r][1];
        }
        // y-regs <- y1 (thread-own reload)
        #pragma unroll
        for (int r = 0; r < 4; r++) {
          float2 yu = *(const float2*)(yalt + (r0+r)*HID + c0);
          float2 yv = *(const float2*)(yalt + ARR + (r0+r)*HID + c0);
          yUr[r][0] = yu.x; yUr[r][1] = yu.y;
          yVr[r][0] = yv.x; yVr[r][1] = yv.y;
        }
        last_t = t; t = t + dt; p ^= 1;
      }
      // reject: k0/y regs intact; nothing to restore
      dt = dt * factor;
      __syncthreads();   // protect y buffers / P before next iteration
    }

    // evaluate interpolation polynomial at the target and store
    float xr = (tf - last_t) / (t - last_t);
    const float* Pc = Pb0 + pp*PH;
    #pragma unroll
    for (int q = 0; q < 2; q++) {
      int e4 = tid + q*256;
      float4 A4 = ((const float4*)Pc)[e4];
      float4 B4 = ((const float4*)(Pc +   ARR))[e4];
      float4 C4 = ((const float4*)(Pc + 2*ARR))[e4];
      float4 D4 = ((const float4*)(Pc + 3*ARR))[e4];
      float4 E4 = ((const float4*)(Pc + 4*ARR))[e4];
      float4 o;
      o.x = fmaf(fmaf(fmaf(fmaf(A4.x, xr, B4.x), xr, C4.x), xr, D4.x), xr, E4.x);
      o.y = fmaf(fmaf(fmaf(fmaf(A4.y, xr, B4.y), xr, C4.y), xr, D4.y), xr, E4.y);
      o.z = fmaf(fmaf(fmaf(fmaf(A4.z, xr, B4.z), xr, C4.z), xr, D4.z), xr, E4.z);
      o.w = fmaf(fmaf(fmaf(fmaf(A4.w, xr, B4.w), xr, C4.w), xr, D4.w), xr, E4.w);
      int e = e4*4; int r = e >> 6; int h = e & 63;
      *(float4*)(out + ((size_t)(brow + r)*FORECAST + (tgt - 1))*HID + h) = o;
    }
  }
}

extern "C" void kernel_launch(void* const* d_in, const int* in_sizes, int n_in,
                              void* d_out, int out_size) {
  (void)in_sizes; (void)n_in; (void)out_size;
  const float* x   = (const float*)d_in[0];
  const float* tri = (const float*)d_in[1];
  float* out = (float*)d_out;
  cudaFuncSetAttribute(sindy_kernel,
                       cudaFuncAttributeMaxDynamicSharedMemorySize, SMEM_BYTES);
  reset_kernel<<<1, 128>>>();
  sindy_kernel<<<NBLK, NTH, SMEM_BYTES>>>(x, tri, out);
}

// round 12
// speedup vs baseline: 6.1793x; 1.1410x over previous
#include <cuda_runtime.h>
#include <math.h>

// ---------------------------------------------------------------------------
// SindyLayer: replicate jax.experimental.ode.odeint (dopri5, rtol=atol=1e-3)
// for dy/dt = iAy split into (u,v): du/dt = -A v, dv/dt = A u, A sym 64x64.
// Output: u (real part) at t = 1..128, shape [4096, 128, 64] f32.
//
// ROUND-12: A stored as column-parity split (AE = even cols, AO = odd cols),
// kp-major, so the two per-kp A loads are lane-contiguous (16B * lane) and
// bank-conflict-free: 4 crossbar cycles instead of 8 each. Values and FFMA2
// order unchanged -> bitwise-identical trajectory. Everything else is the
// round-11 kernel (k0,k2,k3,k5,k6 register-resident; split publish/gather
// reduction with speculative interp; replay-deterministic controller).
// ---------------------------------------------------------------------------

#define HID      64
#define RPB      32
#define NTH      256
#define NBLK     128
#define FORECAST 128
#define ARR      2048            // floats per (u or v) array per block
#define YSZ      4096            // u+v

// smem layout (floats)
#define OFF_A 0                        // AE: 2048 floats, AO: 2048 floats
#define OFF_Y 4096                     // two parity y buffers [u|v]
#define OFF_K (OFF_Y + 2*YSZ)          // 2 k slots: KS1, KS4 (init: f0, f1)
#define OFF_P (OFF_K + 2*YSZ)          // interp: 2 parity x 5 arrays (u only)
#define PH    (5*ARR)
#define OFF_R (OFF_P + 2*PH)           // reduction scratch
#define SM_FLOATS (OFF_R + 8 + 2*NBLK + 8)
#define SMEM_BYTES (SM_FLOATS*4)       // ~165 KB

typedef unsigned long long u64;

// ---- global controller state (persistent; g_seq reset each launch) ----
__device__ float    g_val[2][2*NBLK];  // double-buffered payload (2 channels)
__device__ unsigned g_seq[NBLK];       // per-block monotonically increasing round id

// Dopri5 tableau exactly as in jax/experimental/ode.py
__device__ constexpr float BETAc[6][6] = {
  {(float)(1.0/5.0), 0.f, 0.f, 0.f, 0.f, 0.f},
  {(float)(3.0/40.0), (float)(9.0/40.0), 0.f, 0.f, 0.f, 0.f},
  {(float)(44.0/45.0), (float)(-56.0/15.0), (float)(32.0/9.0), 0.f, 0.f, 0.f},
  {(float)(19372.0/6561.0), (float)(-25360.0/2187.0), (float)(64448.0/6561.0),
   (float)(-212.0/729.0), 0.f, 0.f},
  {(float)(9017.0/3168.0), (float)(-355.0/33.0), (float)(46732.0/5247.0),
   (float)(49.0/176.0), (float)(-5103.0/18656.0), 0.f},
  {(float)(35.0/384.0), 0.f, (float)(500.0/1113.0), (float)(125.0/192.0),
   (float)(-2187.0/6784.0), (float)(11.0/84.0)}
};

// ---- packed f32x2 helpers (FFMA2 path for rhs) ----
__device__ __forceinline__ void ffma2(u64& d, u64 a, u64 b) {
  asm("fma.rn.f32x2 %0, %1, %2, %0;" : "+l"(d) : "l"(a), "l"(b));
}
__device__ __forceinline__ float2 unpack2(u64 v) {
  unsigned lo, hi;
  asm("mov.b64 {%0, %1}, %2;" : "=r"(lo), "=r"(hi) : "l"(v));
  return make_float2(__uint_as_float(lo), __uint_as_float(hi));
}

// Deterministic block-wide sum; result uniform across all 256 threads.
__device__ __forceinline__ float block_sum(float v, float* red) {
  __syncthreads();
  #pragma unroll
  for (int o = 16; o; o >>= 1) v += __shfl_down_sync(0xffffffffu, v, o);
  if ((threadIdx.x & 31) == 0) red[threadIdx.x >> 5] = v;
  __syncthreads();
  float s = red[0];
  #pragma unroll
  for (int w = 1; w < NTH/32; w++) s += red[w];
  return s;
}

__device__ __forceinline__ unsigned ld_seq_cg(const unsigned* p) {
  unsigned v;
  asm volatile("ld.global.cg.u32 %0, [%1];" : "=r"(v) : "l"(p));
  return v;
}

// Release: payload __stcg -> __threadfence -> atomicExch(seq, rno).
__device__ __forceinline__ void gs_publish(float v, float* red, unsigned rno) {
  const int par = rno & 1;
  float b0 = block_sum(v, red);
  if (threadIdx.x == 0) {
    __stcg(&g_val[par][blockIdx.x], b0);
    __threadfence();
    atomicExch(&g_seq[blockIdx.x], rno);
  }
}
// Acquire: per-slot spin, fence, pull to SMEM, fixed-order sum (bitwise-uniform).
__device__ __forceinline__ float gs_gather(float* red, unsigned rno) {
  const int par = rno & 1;
  float* red2 = red + 8;
  const int b = threadIdx.x;
  if (b < NBLK) {
    while (ld_seq_cg(&g_seq[b]) < rno) __nanosleep(32);
    __threadfence();
    red2[b] = __ldcg(&g_val[par][b]);
  }
  __syncthreads();
  float a0 = 0.f;
  for (int i = 0; i < NBLK; i++) a0 += red2[i];
  return a0;
}

// Two-channel variant for init (publish+gather fused; doubles as grid barrier).
__device__ __forceinline__ void global_sum2(float v0, float v1, bool two,
                                            float* red, unsigned rno,
                                            float& s0, float& s1) {
  const int par = rno & 1;
  float b0 = block_sum(v0, red);
  float b1 = two ? block_sum(v1, red) : 0.f;
  float* red2 = red + 8;
  if (threadIdx.x == 0) {
    __stcg(&g_val[par][blockIdx.x], b0);
    if (two) __stcg(&g_val[par][NBLK + blockIdx.x], b1);
    __threadfence();
    atomicExch(&g_seq[blockIdx.x], rno);
  }
  const int b = threadIdx.x;
  if (b < NBLK) {
    while (ld_seq_cg(&g_seq[b]) < rno) __nanosleep(32);
    __threadfence();
    red2[b] = __ldcg(&g_val[par][b]);
    if (two) red2[NBLK + b] = __ldcg(&g_val[par][NBLK + b]);
  }
  __syncthreads();
  float a0 = 0.f, a1 = 0.f;
  for (int i = 0; i < NBLK; i++) {
    a0 += red2[i];
    if (two) a1 += red2[NBLK + i];
  }
  s0 = a0; s1 = a1;
}

// RHS: k_u = -(v @ A^T), k_v = (u @ A^T). Thread owns 4 rows x 2 cols.
// A loads from parity-split arrays: AE2[kp*32+j] / AO2[kp*32+j], j = lane —
// lane-contiguous 16B -> conflict-free. Values & op order identical to rd 11.
template<bool TOREG, bool TOSM>
__device__ __forceinline__ void rhs_eval(const float* __restrict__ y,
                                         float* __restrict__ kd,
                                         const float* __restrict__ Apk,
                                         int c0, int r0,
                                         float (&oU)[4][2], float (&oV)[4][2])
{
  const float* yu = y;
  const float* yv = y + ARR;
  const ulonglong2* __restrict__ AE2 = (const ulonglong2*)Apk;
  const ulonglong2* __restrict__ AO2 = (const ulonglong2*)(Apk + ARR);
  const int j = c0 >> 1;               // lane index 0..31
  u64 aU[4][2], aV[4][2];
  #pragma unroll
  for (int r = 0; r < 4; r++) {
    #pragma unroll
    for (int cc = 0; cc < 2; cc++) { aU[r][cc] = 0ull; aV[r][cc] = 0ull; }
  }
  #pragma unroll 4
  for (int kp = 0; kp < 16; kp++) {
    ulonglong2 A0 = AE2[kp*32 + j];    // col c0   : A[c0][4kp..4kp+3]
    ulonglong2 A1 = AO2[kp*32 + j];    // col c0+1 : A[c0+1][4kp..4kp+3]
    #pragma unroll
    for (int r = 0; r < 4; r++) {
      const int off = (r0 + r)*HID + kp*4;
      ulonglong2 v2 = *(const ulonglong2*)(yv + off);   // broadcast
      ulonglong2 u2 = *(const ulonglong2*)(yu + off);   // broadcast
      ffma2(aU[r][0], A0.x, v2.x); ffma2(aU[r][0], A0.y, v2.y);
      ffma2(aV[r][0], A0.x, u2.x); ffma2(aV[r][0], A0.y, u2.y);
      ffma2(aU[r][1], A1.x, v2.x); ffma2(aU[r][1], A1.y, v2.y);
      ffma2(aV[r][1], A1.x, u2.x); ffma2(aV[r][1], A1.y, u2.y);
    }
  }
  #pragma unroll
  for (int r = 0; r < 4; r++) {
    float2 su0 = unpack2(aU[r][0]), su1 = unpack2(aU[r][1]);
    float2 sv0 = unpack2(aV[r][0]), sv1 = unpack2(aV[r][1]);
    float2 ku = make_float2(-(su0.x + su0.y), -(su1.x + su1.y));
    float2 kv = make_float2( (sv0.x + sv0.y),  (sv1.x + sv1.y));
    if (TOSM) {
      *(float2*)(kd + (r0+r)*HID + c0)       = ku;
      *(float2*)(kd + ARR + (r0+r)*HID + c0) = kv;
    }
    if (TOREG) {
      oU[r][0] = ku.x; oU[r][1] = ku.y;
      oV[r][0] = kv.x; oV[r][1] = kv.y;
    }
  }
}

__global__ void reset_kernel() {
  if (threadIdx.x < NBLK) g_seq[threadIdx.x] = 0u;
}

// Stage-state build helpers (identical per-element ops as rounds 10/11).
#define AXREG(B, KU, KV) { const float b_ = (B); \
  au.x = fmaf(b_, KU[r][0], au.x); au.y = fmaf(b_, KU[r][1], au.y); \
  av.x = fmaf(b_, KV[r][0], av.x); av.y = fmaf(b_, KV[r][1], av.y); }
#define AXSM(B, BASE) { const float b_ = (B); \
  float2 tu_ = *(const float2*)((BASE) + (r0+r)*HID + c0); \
  float2 tv_ = *(const float2*)((BASE) + ARR + (r0+r)*HID + c0); \
  au.x = fmaf(b_, tu_.x, au.x); au.y = fmaf(b_, tu_.y, au.y); \
  av.x = fmaf(b_, tv_.x, av.x); av.y = fmaf(b_, tv_.y, av.y); }
#define AXEND { float2 ou_, ov_; \
  ou_.x = fmaf(dt, au.x, yUr[r][0]); ou_.y = fmaf(dt, au.y, yUr[r][1]); \
  ov_.x = fmaf(dt, av.x, yVr[r][0]); ov_.y = fmaf(dt, av.y, yVr[r][1]); \
  *(float2*)(yalt + (r0+r)*HID + c0)       = ou_; \
  *(float2*)(yalt + ARR + (r0+r)*HID + c0) = ov_; }
#define AXBEGIN float2 au = make_float2(0.f,0.f), av = make_float2(0.f,0.f);

__global__ void __launch_bounds__(NTH, 1)
sindy_kernel(const float* __restrict__ x,
             const float* __restrict__ tri,
             float* __restrict__ out)
{
  extern __shared__ float sm[];
  const int tid  = threadIdx.x;
  const int c0   = (tid & 31) * 2;      // 2 adjacent columns
  const int r0   = (tid >> 5) * 4;      // warp owns 4 rows
  const int brow = blockIdx.x * RPB;

  float* Apk = sm + OFF_A;
  float* K   = sm + OFF_K;              // KS1 = K, KS4 = K + YSZ
  float* KS1 = K;
  float* KS4 = K + YSZ;
  float* Pb0 = sm + OFF_P;
  float* RED = sm + OFF_R;

  unsigned rno = 1;     // reduction round id (uniform across grid)
  int pp = 0;           // P parity (valid interp coefficients)

  // per-thread element registers (rows r0..r0+3, cols c0,c0+1)
  float yUr[4][2], yVr[4][2];
  float kU0[4][2], kV0[4][2];
  float kU2[4][2], kV2[4][2];
  float kU3[4][2], kV3[4][2];
  float kU5[4][2], kV5[4][2];
  float kU6[4][2], kV6[4][2];

  const float CE0 = (float)(35.0/384.0 - 1951.0/21600.0);
  const float CE2 = (float)(500.0/1113.0 - 22642.0/50085.0);
  const float CE3 = (float)(125.0/192.0 - 451.0/720.0);
  const float CE4 = (float)(-2187.0/6784.0 + 12231.0/42400.0);
  const float CE5 = (float)(11.0/84.0 - 649.0/6300.0);
  const float CE6 = (float)(-1.0/60.0);
  const float CM0 = (float)(6025192743.0/30085553152.0/2.0);
  const float CM2 = (float)(51252292925.0/65400821598.0/2.0);
  const float CM3 = (float)(-2691868925.0/45128329728.0/2.0);
  const float CM4 = (float)(187940372067.0/1594534317056.0/2.0);
  const float CM5 = (float)(-1776094331.0/19743644256.0/2.0);
  const float CM6 = (float)(11237099.0/235043384.0/2.0);

  // Build parity-split kp-major A:
  //  AE[kp*128 + j*4 + m] = A[2j  ][kp*4+m]   (floats; 16B per (kp,j))
  //  AO[kp*128 + j*4 + m] = A[2j+1][kp*4+m]
  for (int idx = tid; idx < HID*HID; idx += NTH) {
    int half = idx >> 11;              // 0 = even cols, 1 = odd cols
    int rem  = idx & 2047;
    int kp   = rem >> 7;
    int w    = rem & 127;
    int jj   = w >> 2, m = w & 3;
    int cc   = 2*jj + half;
    int k    = kp*4 + m;
    int R = cc > k ? cc : k, C = cc > k ? k : cc;
    Apk[half*ARR + kp*128 + jj*4 + m] = tri[R*(R+1)/2 + C];
  }

  // y0 = (x, 0); emit output slice t=1 (== y0 per odeint semantics)
  {
    float* Y0 = sm + OFF_Y;
    #pragma unroll
    for (int q = 0; q < 2; q++) {
      int e4 = tid + q*256;
      float4 xv = ((const float4*)x)[brow*16 + e4];
      ((float4*)Y0)[e4]         = xv;
      ((float4*)(Y0 + ARR))[e4] = make_float4(0.f, 0.f, 0.f, 0.f);
      int e = e4*4; int r = e >> 6; int h = e & 63;
      *(float4*)(out + ((size_t)(brow + r)*FORECAST + 0)*HID + h) = xv;
    }
  }
  __syncthreads();

  int p = 0;
  float* ycur = sm + OFF_Y;
  float* yalt = sm + OFF_Y + YSZ;

  // f0 -> k0 regs (FSAL seed) + SMEM slot KS1 for init norms
  rhs_eval<true, true>(ycur, K, Apk, c0, r0, kU0, kV0);
  __syncthreads();

  // ---- initial_step_size (Hairer, order=4), GLOBAL norms (unchanged) ----
  float dt;
  {
    float s0 = 0.f, s1 = 0.f;
    #pragma unroll
    for (int q = 0; q < 4; q++) {
      int e4 = tid + q*256;
      float4 y4 = ((const float4*)ycur)[e4];
      float4 f4 = ((const float4*)K)[e4];
      float ys[4] = {y4.x, y4.y, y4.z, y4.w};
      float fs[4] = {f4.x, f4.y, f4.z, f4.w};
      #pragma unroll
      for (int m = 0; m < 4; m++) {
        float sc = 1e-3f + 1e-3f*fabsf(ys[m]);
        float a0 = ys[m]/sc, a1 = fs[m]/sc;
        s0 = fmaf(a0, a0, s0); s1 = fmaf(a1, a1, s1);
      }
    }
    float t0s, t1s;
    global_sum2(s0, s1, true, RED, rno, t0s, t1s); rno++;
    float d0 = sqrtf(t0s);
    float d1 = sqrtf(t1s);
    float h0 = (d0 < 1e-5f || d1 < 1e-5f) ? 1e-6f : 0.01f*d0/d1;
    #pragma unroll
    for (int q = 0; q < 4; q++) {
      int e4 = tid + q*256;
      float4 y4 = ((const float4*)ycur)[e4];
      float4 f4 = ((const float4*)K)[e4];
      float4 r4;
      r4.x = fmaf(h0, f4.x, y4.x); r4.y = fmaf(h0, f4.y, y4.y);
      r4.z = fmaf(h0, f4.z, y4.z); r4.w = fmaf(h0, f4.w, y4.w);
      ((float4*)yalt)[e4] = r4;
    }
    __syncthreads();
    rhs_eval<false, true>(yalt, K + YSZ, Apk, c0, r0, kU0, kV0);  // f1 probe
    __syncthreads();
    float s2 = 0.f;
    #pragma unroll
    for (int q = 0; q < 4; q++) {
      int e4 = tid + q*256;
      float4 y4  = ((const float4*)ycur)[e4];
      float4 f0v = ((const float4*)K)[e4];
      float4 f1v = ((const float4*)(K + YSZ))[e4];
      float ys[4] = {y4.x, y4.y, y4.z, y4.w};
      float a0[4] = {f0v.x, f0v.y, f0v.z, f0v.w};
      float a1[4] = {f1v.x, f1v.y, f1v.z, f1v.w};
      #pragma unroll
      for (int m = 0; m < 4; m++) {
        float sc = 1e-3f + 1e-3f*fabsf(ys[m]);
        float d = (a1[m] - a0[m])/sc;
        s2 = fmaf(d, d, s2);
      }
    }
    float t2s, dum;
    global_sum2(s2, 0.f, false, RED, rno, t2s, dum); rno++;
    float d2 = sqrtf(t2s) / h0;
    float h1;
    if (d1 <= 1e-15f && d2 <= 1e-15f) h1 = fmaxf(1e-6f, h0*1e-3f);
    else                              h1 = powf(0.01f/fmaxf(d1, d2), 0.2f);
    dt = fminf(100.f*h0, h1);
  }

  // load thread-own y elements into registers
  #pragma unroll
  for (int r = 0; r < 4; r++) {
    float2 yu = *(const float2*)(ycur + (r0+r)*HID + c0);
    float2 yv = *(const float2*)(ycur + ARR + (r0+r)*HID + c0);
    yUr[r][0] = yu.x; yUr[r][1] = yu.y;
    yVr[r][0] = yv.x; yVr[r][1] = yv.y;
  }

  float t = 1.f, last_t = 1.f;

  // ---- main scan over output targets ----
  for (int tgt = 2; tgt <= FORECAST; tgt++) {
    float tf = (float)tgt;
    int guard = 0;
    while (t < tf && dt > 0.f && guard < 100000) {
      guard++;
      ycur = sm + OFF_Y + p*YSZ;
      yalt = sm + OFF_Y + (p^1)*YSZ;

      // ---- stages 1..6 (warp-local; k1,k4 via thread-own SMEM slots) ----
      // S1 -> k1 (SMEM)
      #pragma unroll
      for (int r = 0; r < 4; r++) { AXBEGIN AXREG(BETAc[0][0], kU0, kV0) AXEND }
      __syncwarp();
      rhs_eval<false, true>(yalt, KS1, Apk, c0, r0, kU0, kV0);
      __syncwarp();
      // S2 -> k2 (regs)
      #pragma unroll
      for (int r = 0; r < 4; r++) { AXBEGIN
        AXREG(BETAc[1][0], kU0, kV0) AXSM(BETAc[1][1], KS1) AXEND }
      __syncwarp();
      rhs_eval<true, false>(yalt, K, Apk, c0, r0, kU2, kV2);
      __syncwarp();
      // S3 -> k3 (regs)
      #pragma unroll
      for (int r = 0; r < 4; r++) { AXBEGIN
        AXREG(BETAc[2][0], kU0, kV0) AXSM(BETAc[2][1], KS1)
        AXREG(BETAc[2][2], kU2, kV2) AXEND }
      __syncwarp();
      rhs_eval<true, false>(yalt, K, Apk, c0, r0, kU3, kV3);
      __syncwarp();
      // S4 -> k4 (SMEM)
      #pragma unroll
      for (int r = 0; r < 4; r++) { AXBEGIN
        AXREG(BETAc[3][0], kU0, kV0) AXSM(BETAc[3][1], KS1)
        AXREG(BETAc[3][2], kU2, kV2) AXREG(BETAc[3][3], kU3, kV3) AXEND }
      __syncwarp();
      rhs_eval<false, true>(yalt, KS4, Apk, c0, r0, kU0, kV0);
      __syncwarp();
      // S5 -> k5 (regs)
      #pragma unroll
      for (int r = 0; r < 4; r++) { AXBEGIN
        AXREG(BETAc[4][0], kU0, kV0) AXSM(BETAc[4][1], KS1)
        AXREG(BETAc[4][2], kU2, kV2) AXREG(BETAc[4][3], kU3, kV3)
        AXSM(BETAc[4][4], KS4) AXEND }
      __syncwarp();
      rhs_eval<true, false>(yalt, K, Apk, c0, r0, kU5, kV5);
      __syncwarp();
      // S6 -> k6 (regs); beta[5][1] == 0 -> k1 term skipped
      #pragma unroll
      for (int r = 0; r < 4; r++) { AXBEGIN
        AXREG(BETAc[5][0], kU0, kV0)
        AXREG(BETAc[5][2], kU2, kV2) AXREG(BETAc[5][3], kU3, kV3)
        AXSM(BETAc[5][4], KS4) AXREG(BETAc[5][5], kU5, kV5) AXEND }
      __syncwarp();
      rhs_eval<true, false>(yalt, K, Apk, c0, r0, kU6, kV6);
      __syncwarp();
      // yalt == y1 (FSAL)

      // ---- error-ratio partial from registers + thread-own SMEM ----
      float ss = 0.f;
      #pragma unroll
      for (int r = 0; r < 4; r++) {
        float2 k4u = *(const float2*)(KS4 + (r0+r)*HID + c0);
        float2 k4v = *(const float2*)(KS4 + ARR + (r0+r)*HID + c0);
        float2 y1u = *(const float2*)(yalt + (r0+r)*HID + c0);
        float2 y1v = *(const float2*)(yalt + ARR + (r0+r)*HID + c0);
        #define EC(K0,K2,K3,K4,K5,K6,Y0,Y1) { \
          float er_ = dt*(CE0*(K0) + CE2*(K2) + CE3*(K3) + CE4*(K4) + CE5*(K5) + CE6*(K6)); \
          float tol_ = 1e-3f + 1e-3f*fmaxf(fabsf(Y0), fabsf(Y1)); \
          float rr_ = er_/tol_; ss = fmaf(rr_, rr_, ss); }
        EC(kU0[r][0],kU2[r][0],kU3[r][0],k4u.x,kU5[r][0],kU6[r][0],yUr[r][0],y1u.x)
        EC(kU0[r][1],kU2[r][1],kU3[r][1],k4u.y,kU5[r][1],kU6[r][1],yUr[r][1],y1u.y)
        EC(kV0[r][0],kV2[r][0],kV3[r][0],k4v.x,kV5[r][0],kV6[r][0],yVr[r][0],y1v.x)
        EC(kV0[r][1],kV2[r][1],kV3[r][1],k4v.y,kV5[r][1],kV6[r][1],yVr[r][1],y1v.y)
        #undef EC
      }
      gs_publish(ss, RED, rno);

      // ---- speculative interp coefficients (u only) into P[pp^1] ----
      {
        float* Pn = Pb0 + (pp^1)*PH;
        #pragma unroll
        for (int r = 0; r < 4; r++) {
          float2 k4u = *(const float2*)(KS4 + (r0+r)*HID + c0);
          float2 y1u = *(const float2*)(yalt + (r0+r)*HID + c0);
          float2 A2f, B2f, C2f, D2f, E2f;
          #define IC(W, K0,K2,K3,K4,K5,K6,Y0,Y1) { \
            float ym = fmaf(dt, CM0*(K0) + CM2*(K2) + CM3*(K3) + CM4*(K4) + CM5*(K5) + CM6*(K6), (Y0)); \
            float D0 = dt*(K0), D1 = dt*(K6); \
            A2f.W = -2.f*D0 + 2.f*D1 -  8.f*(Y0) -  8.f*(Y1) + 16.f*ym; \
            B2f.W =  5.f*D0 - 3.f*D1 + 18.f*(Y0) + 14.f*(Y1) - 32.f*ym; \
            C2f.W = -4.f*D0 +     D1 - 11.f*(Y0) -  5.f*(Y1) + 16.f*ym; \
            D2f.W = D0; E2f.W = (Y0); }
          IC(x, kU0[r][0],kU2[r][0],kU3[r][0],k4u.x,kU5[r][0],kU6[r][0],yUr[r][0],y1u.x)
          IC(y, kU0[r][1],kU2[r][1],kU3[r][1],k4u.y,kU5[r][1],kU6[r][1],yUr[r][1],y1u.y)
          #undef IC
          *(float2*)(Pn + 0*ARR + (r0+r)*HID + c0) = A2f;
          *(float2*)(Pn + 1*ARR + (r0+r)*HID + c0) = B2f;
          *(float2*)(Pn + 2*ARR + (r0+r)*HID + c0) = C2f;
          *(float2*)(Pn + 3*ARR + (r0+r)*HID + c0) = D2f;
          *(float2*)(Pn + 4*ARR + (r0+r)*HID + c0) = E2f;
        }
      }

      float tss = gs_gather(RED, rno); rno++;
      float ratio  = sqrtf(tss * (1.f/524288.f));
      float er     = fmaxf(ratio, 1e-10f);
      float dfac   = (ratio < 1.f) ? 1.f : 0.2f;
      float factor = fminf(10.f, fmaxf(0.9f*powf(er, -0.2f), dfac));
      bool  accept = (ratio <= 1.f);

      if (accept) {
        pp ^= 1;                         // speculative P becomes valid
        // FSAL: k0 <- k6 (register copies)
        #pragma unroll
        for (int r = 0; r < 4; r++) {
          kU0[r][0] = kU6[r][0]; kU0[r][1] = kU6[r][1];
          kV0[r][0] = kV6[r][0]; kV0[r][1] = kV6[r][1];
        }
        // y-regs <- y1 (thread-own reload)
        #pragma unroll
        for (int r = 0; r < 4; r++) {
          float2 yu = *(const float2*)(yalt + (r0+r)*HID + c0);
          float2 yv = *(const float2*)(yalt + ARR + (r0+r)*HID + c0);
          yUr[r][0] = yu.x; yUr[r][1] = yu.y;
          yVr[r][0] = yv.x; yVr[r][1] = yv.y;
        }
        last_t = t; t = t + dt; p ^= 1;
      }
      // reject: k0/y regs intact; nothing to restore
      dt = dt * factor;
      __syncthreads();   // protect y buffers / P before next iteration
    }

    // evaluate interpolation polynomial at the target and store
    float xr = (tf - last_t) / (t - last_t);
    const float* Pc = Pb0 + pp*PH;
    #pragma unroll
    for (int q = 0; q < 2; q++) {
      int e4 = tid + q*256;
      float4 A4 = ((const float4*)Pc)[e4];
      float4 B4 = ((const float4*)(Pc +   ARR))[e4];
      float4 C4 = ((const float4*)(Pc + 2*ARR))[e4];
      float4 D4 = ((const float4*)(Pc + 3*ARR))[e4];
      float4 E4 = ((const float4*)(Pc + 4*ARR))[e4];
      float4 o;
      o.x = fmaf(fmaf(fmaf(fmaf(A4.x, xr, B4.x), xr, C4.x), xr, D4.x), xr, E4.x);
      o.y = fmaf(fmaf(fmaf(fmaf(A4.y, xr, B4.y), xr, C4.y), xr, D4.y), xr, E4.y);
      o.z = fmaf(fmaf(fmaf(fmaf(A4.z, xr, B4.z), xr, C4.z), xr, D4.z), xr, E4.z);
      o.w = fmaf(fmaf(fmaf(fmaf(A4.w, xr, B4.w), xr, C4.w), xr, D4.w), xr, E4.w);
      int e = e4*4; int r = e >> 6; int h = e & 63;
      *(float4*)(out + ((size_t)(brow + r)*FORECAST + (tgt - 1))*HID + h) = o;
    }
  }
}

extern "C" void kernel_launch(void* const* d_in, const int* in_sizes, int n_in,
                              void* d_out, int out_size) {
  (void)in_sizes; (void)n_in; (void)out_size;
  const float* x   = (const float*)d_in[0];
  const float* tri = (const float*)d_in[1];
  float* out = (float*)d_out;
  cudaFuncSetAttribute(sindy_kernel,
                       cudaFuncAttributeMaxDynamicSharedMemorySize, SMEM_BYTES);
  reset_kernel<<<1, 128>>>();
  sindy_kernel<<<NBLK, NTH, SMEM_BYTES>>>(x, tri, out);
}

// round 13
// speedup vs baseline: 6.4267x; 1.0400x over previous
#include <cuda_runtime.h>
#include <math.h>

// ---------------------------------------------------------------------------
// SindyLayer: replicate jax.experimental.ode.odeint (dopri5, rtol=atol=1e-3)
// for dy/dt = iAy split into (u,v): du/dt = -A v, dv/dt = A u, A sym 64x64.
// Output: u (real part) at t = 1..128, shape [4096, 128, 64] f32.
//
// ROUND-13: A for kp 0..7 cached in registers (64 regs) -> halves the
// per-rhs A crossbar traffic (each warp re-read all 16KB of A 6x/step).
// Paid for by demoting k2,k3,k5 to SMEM slots (k0,k6 stay register-resident
// for the FSAL pair). All per-element arithmetic and iteration order is
// unchanged -> bitwise-identical trajectory vs rounds 10-12.
// Controller: per-slot release/acquire global reduction, split publish/gather
// with speculative interp (double-buffered P), replay-deterministic.
// ---------------------------------------------------------------------------

#define HID      64
#define RPB      32
#define NTH      256
#define NBLK     128
#define FORECAST 128
#define ARR      2048            // floats per (u or v) array per block
#define YSZ      4096            // u+v

// smem layout (floats)
#define OFF_A 0                        // AE: 2048 floats, AO: 2048 floats
#define OFF_Y 4096                     // two parity y buffers [u|v]
#define OFF_K (OFF_Y + 2*YSZ)          // 5 k slots: k1..k5
#define OFF_P (OFF_K + 5*YSZ)          // interp: 2 parity x 5 arrays (u only)
#define PH    (5*ARR)
#define OFF_R (OFF_P + 2*PH)           // reduction scratch
#define SM_FLOATS (OFF_R + 8 + 2*NBLK + 8)
#define SMEM_BYTES (SM_FLOATS*4)       // ~214 KB

typedef unsigned long long u64;

// ---- global controller state (persistent; g_seq reset each launch) ----
__device__ float    g_val[2][2*NBLK];  // double-buffered payload (2 channels)
__device__ unsigned g_seq[NBLK];       // per-block monotonically increasing round id

// Dopri5 tableau exactly as in jax/experimental/ode.py
__device__ constexpr float BETAc[6][6] = {
  {(float)(1.0/5.0), 0.f, 0.f, 0.f, 0.f, 0.f},
  {(float)(3.0/40.0), (float)(9.0/40.0), 0.f, 0.f, 0.f, 0.f},
  {(float)(44.0/45.0), (float)(-56.0/15.0), (float)(32.0/9.0), 0.f, 0.f, 0.f},
  {(float)(19372.0/6561.0), (float)(-25360.0/2187.0), (float)(64448.0/6561.0),
   (float)(-212.0/729.0), 0.f, 0.f},
  {(float)(9017.0/3168.0), (float)(-355.0/33.0), (float)(46732.0/5247.0),
   (float)(49.0/176.0), (float)(-5103.0/18656.0), 0.f},
  {(float)(35.0/384.0), 0.f, (float)(500.0/1113.0), (float)(125.0/192.0),
   (float)(-2187.0/6784.0), (float)(11.0/84.0)}
};

// ---- packed f32x2 helpers (FFMA2 path for rhs) ----
__device__ __forceinline__ void ffma2(u64& d, u64 a, u64 b) {
  asm("fma.rn.f32x2 %0, %1, %2, %0;" : "+l"(d) : "l"(a), "l"(b));
}
__device__ __forceinline__ float2 unpack2(u64 v) {
  unsigned lo, hi;
  asm("mov.b64 {%0, %1}, %2;" : "=r"(lo), "=r"(hi) : "l"(v));
  return make_float2(__uint_as_float(lo), __uint_as_float(hi));
}

// Deterministic block-wide sum; result uniform across all 256 threads.
__device__ __forceinline__ float block_sum(float v, float* red) {
  __syncthreads();
  #pragma unroll
  for (int o = 16; o; o >>= 1) v += __shfl_down_sync(0xffffffffu, v, o);
  if ((threadIdx.x & 31) == 0) red[threadIdx.x >> 5] = v;
  __syncthreads();
  float s = red[0];
  #pragma unroll
  for (int w = 1; w < NTH/32; w++) s += red[w];
  return s;
}

__device__ __forceinline__ unsigned ld_seq_cg(const unsigned* p) {
  unsigned v;
  asm volatile("ld.global.cg.u32 %0, [%1];" : "=r"(v) : "l"(p));
  return v;
}

// Release: payload __stcg -> __threadfence -> atomicExch(seq, rno).
__device__ __forceinline__ void gs_publish(float v, float* red, unsigned rno) {
  const int par = rno & 1;
  float b0 = block_sum(v, red);
  if (threadIdx.x == 0) {
    __stcg(&g_val[par][blockIdx.x], b0);
    __threadfence();
    atomicExch(&g_seq[blockIdx.x], rno);
  }
}
// Acquire: per-slot spin, fence, pull to SMEM, fixed-order sum (bitwise-uniform).
__device__ __forceinline__ float gs_gather(float* red, unsigned rno) {
  const int par = rno & 1;
  float* red2 = red + 8;
  const int b = threadIdx.x;
  if (b < NBLK) {
    while (ld_seq_cg(&g_seq[b]) < rno) __nanosleep(32);
    __threadfence();
    red2[b] = __ldcg(&g_val[par][b]);
  }
  __syncthreads();
  float a0 = 0.f;
  for (int i = 0; i < NBLK; i++) a0 += red2[i];
  return a0;
}

// Two-channel variant for init (publish+gather fused; doubles as grid barrier).
__device__ __forceinline__ void global_sum2(float v0, float v1, bool two,
                                            float* red, unsigned rno,
                                            float& s0, float& s1) {
  const int par = rno & 1;
  float b0 = block_sum(v0, red);
  float b1 = two ? block_sum(v1, red) : 0.f;
  float* red2 = red + 8;
  if (threadIdx.x == 0) {
    __stcg(&g_val[par][blockIdx.x], b0);
    if (two) __stcg(&g_val[par][NBLK + blockIdx.x], b1);
    __threadfence();
    atomicExch(&g_seq[blockIdx.x], rno);
  }
  const int b = threadIdx.x;
  if (b < NBLK) {
    while (ld_seq_cg(&g_seq[b]) < rno) __nanosleep(32);
    __threadfence();
    red2[b] = __ldcg(&g_val[par][b]);
    if (two) red2[NBLK + b] = __ldcg(&g_val[par][NBLK + b]);
  }
  __syncthreads();
  float a0 = 0.f, a1 = 0.f;
  for (int i = 0; i < NBLK; i++) {
    a0 += red2[i];
    if (two) a1 += red2[NBLK + i];
  }
  s0 = a0; s1 = a1;
}

// RHS: k_u = -(v @ A^T), k_v = (u @ A^T). Thread owns 4 rows x 2 cols.
// kp 0..7: A from registers (ArE/ArO). kp 8..15: A from parity-split SMEM.
// kp ascending; per-(row,col) even/odd-k FFMA2 order identical to rounds 3-12.
template<bool TOREG, bool TOSM>
__device__ __forceinline__ void rhs_eval(const float* __restrict__ y,
                                         float* __restrict__ kd,
                                         const float* __restrict__ Apk,
                                         const ulonglong2 (&ArE)[8],
                                         const ulonglong2 (&ArO)[8],
                                         int c0, int r0,
                                         float (&oU)[4][2], float (&oV)[4][2])
{
  const float* yu = y;
  const float* yv = y + ARR;
  const ulonglong2* __restrict__ AE2 = (const ulonglong2*)Apk;
  const ulonglong2* __restrict__ AO2 = (const ulonglong2*)(Apk + ARR);
  const int j = c0 >> 1;               // lane index 0..31
  u64 aU[4][2], aV[4][2];
  #pragma unroll
  for (int r = 0; r < 4; r++) {
    #pragma unroll
    for (int cc = 0; cc < 2; cc++) { aU[r][cc] = 0ull; aV[r][cc] = 0ull; }
  }
  // kp 0..7: register-cached A
  #pragma unroll
  for (int kp = 0; kp < 8; kp++) {
    ulonglong2 A0 = ArE[kp];
    ulonglong2 A1 = ArO[kp];
    #pragma unroll
    for (int r = 0; r < 4; r++) {
      const int off = (r0 + r)*HID + kp*4;
      ulonglong2 v2 = *(const ulonglong2*)(yv + off);   // broadcast
      ulonglong2 u2 = *(const ulonglong2*)(yu + off);   // broadcast
      ffma2(aU[r][0], A0.x, v2.x); ffma2(aU[r][0], A0.y, v2.y);
      ffma2(aV[r][0], A0.x, u2.x); ffma2(aV[r][0], A0.y, u2.y);
      ffma2(aU[r][1], A1.x, v2.x); ffma2(aU[r][1], A1.y, v2.y);
      ffma2(aV[r][1], A1.x, u2.x); ffma2(aV[r][1], A1.y, u2.y);
    }
  }
  // kp 8..15: A from SMEM (conflict-free lane-contiguous)
  #pragma unroll 4
  for (int kp = 8; kp < 16; kp++) {
    ulonglong2 A0 = AE2[kp*32 + j];
    ulonglong2 A1 = AO2[kp*32 + j];
    #pragma unroll
    for (int r = 0; r < 4; r++) {
      const int off = (r0 + r)*HID + kp*4;
      ulonglong2 v2 = *(const ulonglong2*)(yv + off);   // broadcast
      ulonglong2 u2 = *(const ulonglong2*)(yu + off);   // broadcast
      ffma2(aU[r][0], A0.x, v2.x); ffma2(aU[r][0], A0.y, v2.y);
      ffma2(aV[r][0], A0.x, u2.x); ffma2(aV[r][0], A0.y, u2.y);
      ffma2(aU[r][1], A1.x, v2.x); ffma2(aU[r][1], A1.y, v2.y);
      ffma2(aV[r][1], A1.x, u2.x); ffma2(aV[r][1], A1.y, u2.y);
    }
  }
  #pragma unroll
  for (int r = 0; r < 4; r++) {
    float2 su0 = unpack2(aU[r][0]), su1 = unpack2(aU[r][1]);
    float2 sv0 = unpack2(aV[r][0]), sv1 = unpack2(aV[r][1]);
    float2 ku = make_float2(-(su0.x + su0.y), -(su1.x + su1.y));
    float2 kv = make_float2( (sv0.x + sv0.y),  (sv1.x + sv1.y));
    if (TOSM) {
      *(float2*)(kd + (r0+r)*HID + c0)       = ku;
      *(float2*)(kd + ARR + (r0+r)*HID + c0) = kv;
    }
    if (TOREG) {
      oU[r][0] = ku.x; oU[r][1] = ku.y;
      oV[r][0] = kv.x; oV[r][1] = kv.y;
    }
  }
}

__global__ void reset_kernel() {
  if (threadIdx.x < NBLK) g_seq[threadIdx.x] = 0u;
}

// Stage-state build helpers (identical per-element ops as rounds 10-12).
#define AXREG(B, KU, KV) { const float b_ = (B); \
  au.x = fmaf(b_, KU[r][0], au.x); au.y = fmaf(b_, KU[r][1], au.y); \
  av.x = fmaf(b_, KV[r][0], av.x); av.y = fmaf(b_, KV[r][1], av.y); }
#define AXSM(B, BASE) { const float b_ = (B); \
  float2 tu_ = *(const float2*)((BASE) + (r0+r)*HID + c0); \
  float2 tv_ = *(const float2*)((BASE) + ARR + (r0+r)*HID + c0); \
  au.x = fmaf(b_, tu_.x, au.x); au.y = fmaf(b_, tu_.y, au.y); \
  av.x = fmaf(b_, tv_.x, av.x); av.y = fmaf(b_, tv_.y, av.y); }
#define AXEND { float2 ou_, ov_; \
  ou_.x = fmaf(dt, au.x, yUr[r][0]); ou_.y = fmaf(dt, au.y, yUr[r][1]); \
  ov_.x = fmaf(dt, av.x, yVr[r][0]); ov_.y = fmaf(dt, av.y, yVr[r][1]); \
  *(float2*)(yalt + (r0+r)*HID + c0)       = ou_; \
  *(float2*)(yalt + ARR + (r0+r)*HID + c0) = ov_; }
#define AXBEGIN float2 au = make_float2(0.f,0.f), av = make_float2(0.f,0.f);

__global__ void __launch_bounds__(NTH, 1)
sindy_kernel(const float* __restrict__ x,
             const float* __restrict__ tri,
             float* __restrict__ out)
{
  extern __shared__ float sm[];
  const int tid  = threadIdx.x;
  const int c0   = (tid & 31) * 2;      // 2 adjacent columns
  const int r0   = (tid >> 5) * 4;      // warp owns 4 rows
  const int brow = blockIdx.x * RPB;

  float* Apk = sm + OFF_A;
  float* K   = sm + OFF_K;
  float* KS1 = K;
  float* KS2 = K + 1*YSZ;
  float* KS3 = K + 2*YSZ;
  float* KS4 = K + 3*YSZ;
  float* KS5 = K + 4*YSZ;
  float* Pb0 = sm + OFF_P;
  float* RED = sm + OFF_R;

  unsigned rno = 1;     // reduction round id (uniform across grid)
  int pp = 0;           // P parity (valid interp coefficients)

  // per-thread element registers (rows r0..r0+3, cols c0,c0+1)
  float yUr[4][2], yVr[4][2];
  float kU0[4][2], kV0[4][2];
  float kU6[4][2], kV6[4][2];
  ulonglong2 ArE[8], ArO[8];            // A cache, kp 0..7

  const float CE0 = (float)(35.0/384.0 - 1951.0/21600.0);
  const float CE2 = (float)(500.0/1113.0 - 22642.0/50085.0);
  const float CE3 = (float)(125.0/192.0 - 451.0/720.0);
  const float CE4 = (float)(-2187.0/6784.0 + 12231.0/42400.0);
  const float CE5 = (float)(11.0/84.0 - 649.0/6300.0);
  const float CE6 = (float)(-1.0/60.0);
  const float CM0 = (float)(6025192743.0/30085553152.0/2.0);
  const float CM2 = (float)(51252292925.0/65400821598.0/2.0);
  const float CM3 = (float)(-2691868925.0/45128329728.0/2.0);
  const float CM4 = (float)(187940372067.0/1594534317056.0/2.0);
  const float CM5 = (float)(-1776094331.0/19743644256.0/2.0);
  const float CM6 = (float)(11237099.0/235043384.0/2.0);

  // Build parity-split kp-major A:
  //  AE[kp*128 + j*4 + m] = A[2j  ][kp*4+m]
  //  AO[kp*128 + j*4 + m] = A[2j+1][kp*4+m]
  for (int idx = tid; idx < HID*HID; idx += NTH) {
    int half = idx >> 11;
    int rem  = idx & 2047;
    int kp   = rem >> 7;
    int w    = rem & 127;
    int jj   = w >> 2, m = w & 3;
    int cc   = 2*jj + half;
    int k    = kp*4 + m;
    int R = cc > k ? cc : k, C = cc > k ? k : cc;
    Apk[half*ARR + kp*128 + jj*4 + m] = tri[R*(R+1)/2 + C];
  }

  // y0 = (x, 0); emit output slice t=1 (== y0 per odeint semantics)
  {
    float* Y0 = sm + OFF_Y;
    #pragma unroll
    for (int q = 0; q < 2; q++) {
      int e4 = tid + q*256;
      float4 xv = ((const float4*)x)[brow*16 + e4];
      ((float4*)Y0)[e4]         = xv;
      ((float4*)(Y0 + ARR))[e4] = make_float4(0.f, 0.f, 0.f, 0.f);
      int e = e4*4; int r = e >> 6; int h = e & 63;
      *(float4*)(out + ((size_t)(brow + r)*FORECAST + 0)*HID + h) = xv;
    }
  }
  __syncthreads();

  // load A cache (same bits as SMEM parity arrays)
  {
    const ulonglong2* AE2 = (const ulonglong2*)Apk;
    const ulonglong2* AO2 = (const ulonglong2*)(Apk + ARR);
    const int j = c0 >> 1;
    #pragma unroll
    for (int kp = 0; kp < 8; kp++) {
      ArE[kp] = AE2[kp*32 + j];
      ArO[kp] = AO2[kp*32 + j];
    }
  }

  int p = 0;
  float* ycur = sm + OFF_Y;
  float* yalt = sm + OFF_Y + YSZ;

  // f0 -> k0 regs (FSAL seed) + SMEM slot KS1 for init norms
  rhs_eval<true, true>(ycur, K, Apk, ArE, ArO, c0, r0, kU0, kV0);
  __syncthreads();

  // ---- initial_step_size (Hairer, order=4), GLOBAL norms (unchanged) ----
  float dt;
  {
    float s0 = 0.f, s1 = 0.f;
    #pragma unroll
    for (int q = 0; q < 4; q++) {
      int e4 = tid + q*256;
      float4 y4 = ((const float4*)ycur)[e4];
      float4 f4 = ((const float4*)K)[e4];
      float ys[4] = {y4.x, y4.y, y4.z, y4.w};
      float fs[4] = {f4.x, f4.y, f4.z, f4.w};
      #pragma unroll
      for (int m = 0; m < 4; m++) {
        float sc = 1e-3f + 1e-3f*fabsf(ys[m]);
        float a0 = ys[m]/sc, a1 = fs[m]/sc;
        s0 = fmaf(a0, a0, s0); s1 = fmaf(a1, a1, s1);
      }
    }
    float t0s, t1s;
    global_sum2(s0, s1, true, RED, rno, t0s, t1s); rno++;
    float d0 = sqrtf(t0s);
    float d1 = sqrtf(t1s);
    float h0 = (d0 < 1e-5f || d1 < 1e-5f) ? 1e-6f : 0.01f*d0/d1;
    #pragma unroll
    for (int q = 0; q < 4; q++) {
      int e4 = tid + q*256;
      float4 y4 = ((const float4*)ycur)[e4];
      float4 f4 = ((const float4*)K)[e4];
      float4 r4;
      r4.x = fmaf(h0, f4.x, y4.x); r4.y = fmaf(h0, f4.y, y4.y);
      r4.z = fmaf(h0, f4.z, y4.z); r4.w = fmaf(h0, f4.w, y4.w);
      ((float4*)yalt)[e4] = r4;
    }
    __syncthreads();
    rhs_eval<false, true>(yalt, K + YSZ, Apk, ArE, ArO, c0, r0, kU0, kV0);
    __syncthreads();
    float s2 = 0.f;
    #pragma unroll
    for (int q = 0; q < 4; q++) {
      int e4 = tid + q*256;
      float4 y4  = ((const float4*)ycur)[e4];
      float4 f0v = ((const float4*)K)[e4];
      float4 f1v = ((const float4*)(K + YSZ))[e4];
      float ys[4] = {y4.x, y4.y, y4.z, y4.w};
      float a0[4] = {f0v.x, f0v.y, f0v.z, f0v.w};
      float a1[4] = {f1v.x, f1v.y, f1v.z, f1v.w};
      #pragma unroll
      for (int m = 0; m < 4; m++) {
        float sc = 1e-3f + 1e-3f*fabsf(ys[m]);
        float d = (a1[m] - a0[m])/sc;
        s2 = fmaf(d, d, s2);
      }
    }
    float t2s, dum;
    global_sum2(s2, 0.f, false, RED, rno, t2s, dum); rno++;
    float d2 = sqrtf(t2s) / h0;
    float h1;
    if (d1 <= 1e-15f && d2 <= 1e-15f) h1 = fmaxf(1e-6f, h0*1e-3f);
    else                              h1 = powf(0.01f/fmaxf(d1, d2), 0.2f);
    dt = fminf(100.f*h0, h1);
  }

  // load thread-own y elements into registers
  #pragma unroll
  for (int r = 0; r < 4; r++) {
    float2 yu = *(const float2*)(ycur + (r0+r)*HID + c0);
    float2 yv = *(const float2*)(ycur + ARR + (r0+r)*HID + c0);
    yUr[r][0] = yu.x; yUr[r][1] = yu.y;
    yVr[r][0] = yv.x; yVr[r][1] = yv.y;
  }

  float t = 1.f, last_t = 1.f;

  // ---- main scan over output targets ----
  for (int tgt = 2; tgt <= FORECAST; tgt++) {
    float tf = (float)tgt;
    int guard = 0;
    while (t < tf && dt > 0.f && guard < 100000) {
      guard++;
      ycur = sm + OFF_Y + p*YSZ;
      yalt = sm + OFF_Y + (p^1)*YSZ;

      // ---- stages 1..6 (warp-local; k1..k5 in thread-own SMEM slots) ----
      // S1 -> k1
      #pragma unroll
      for (int r = 0; r < 4; r++) { AXBEGIN AXREG(BETAc[0][0], kU0, kV0) AXEND }
      __syncwarp();
      rhs_eval<false, true>(yalt, KS1, Apk, ArE, ArO, c0, r0, kU0, kV0);
      __syncwarp();
      // S2 -> k2
      #pragma unroll
      for (int r = 0; r < 4; r++) { AXBEGIN
        AXREG(BETAc[1][0], kU0, kV0) AXSM(BETAc[1][1], KS1) AXEND }
      __syncwarp();
      rhs_eval<false, true>(yalt, KS2, Apk, ArE, ArO, c0, r0, kU0, kV0);
      __syncwarp();
      // S3 -> k3
      #pragma unroll
      for (int r = 0; r < 4; r++) { AXBEGIN
        AXREG(BETAc[2][0], kU0, kV0) AXSM(BETAc[2][1], KS1)
        AXSM(BETAc[2][2], KS2) AXEND }
      __syncwarp();
      rhs_eval<false, true>(yalt, KS3, Apk, ArE, ArO, c0, r0, kU0, kV0);
      __syncwarp();
      // S4 -> k4
      #pragma unroll
      for (int r = 0; r < 4; r++) { AXBEGIN
        AXREG(BETAc[3][0], kU0, kV0) AXSM(BETAc[3][1], KS1)
        AXSM(BETAc[3][2], KS2) AXSM(BETAc[3][3], KS3) AXEND }
      __syncwarp();
      rhs_eval<false, true>(yalt, KS4, Apk, ArE, ArO, c0, r0, kU0, kV0);
      __syncwarp();
      // S5 -> k5
      #pragma unroll
      for (int r = 0; r < 4; r++) { AXBEGIN
        AXREG(BETAc[4][0], kU0, kV0) AXSM(BETAc[4][1], KS1)
        AXSM(BETAc[4][2], KS2) AXSM(BETAc[4][3], KS3)
        AXSM(BETAc[4][4], KS4) AXEND }
      __syncwarp();
      rhs_eval<false, true>(yalt, KS5, Apk, ArE, ArO, c0, r0, kU0, kV0);
      __syncwarp();
      // S6 -> k6 (regs); beta[5][1] == 0 -> k1 term skipped
      #pragma unroll
      for (int r = 0; r < 4; r++) { AXBEGIN
        AXREG(BETAc[5][0], kU0, kV0)
        AXSM(BETAc[5][2], KS2) AXSM(BETAc[5][3], KS3)
        AXSM(BETAc[5][4], KS4) AXSM(BETAc[5][5], KS5) AXEND }
      __syncwarp();
      rhs_eval<true, false>(yalt, K, Apk, ArE, ArO, c0, r0, kU6, kV6);
      __syncwarp();
      // yalt == y1 (FSAL)

      // ---- error-ratio partial (same value order as rounds 11/12) ----
      float ss = 0.f;
      #pragma unroll
      for (int r = 0; r < 4; r++) {
        float2 k2u = *(const float2*)(KS2 + (r0+r)*HID + c0);
        float2 k2v = *(const float2*)(KS2 + ARR + (r0+r)*HID + c0);
        float2 k3u = *(const float2*)(KS3 + (r0+r)*HID + c0);
        float2 k3v = *(const float2*)(KS3 + ARR + (r0+r)*HID + c0);
        float2 k4u = *(const float2*)(KS4 + (r0+r)*HID + c0);
        float2 k4v = *(const float2*)(KS4 + ARR + (r0+r)*HID + c0);
        float2 k5u = *(const float2*)(KS5 + (r0+r)*HID + c0);
        float2 k5v = *(const float2*)(KS5 + ARR + (r0+r)*HID + c0);
        float2 y1u = *(const float2*)(yalt + (r0+r)*HID + c0);
        float2 y1v = *(const float2*)(yalt + ARR + (r0+r)*HID + c0);
        #define EC(K0,K2,K3,K4,K5,K6,Y0,Y1) { \
          float er_ = dt*(CE0*(K0) + CE2*(K2) + CE3*(K3) + CE4*(K4) + CE5*(K5) + CE6*(K6)); \
          float tol_ = 1e-3f + 1e-3f*fmaxf(fabsf(Y0), fabsf(Y1)); \
          float rr_ = er_/tol_; ss = fmaf(rr_, rr_, ss); }
        EC(kU0[r][0],k2u.x,k3u.x,k4u.x,k5u.x,kU6[r][0],yUr[r][0],y1u.x)
        EC(kU0[r][1],k2u.y,k3u.y,k4u.y,k5u.y,kU6[r][1],yUr[r][1],y1u.y)
        EC(kV0[r][0],k2v.x,k3v.x,k4v.x,k5v.x,kV6[r][0],yVr[r][0],y1v.x)
        EC(kV0[r][1],k2v.y,k3v.y,k4v.y,k5v.y,kV6[r][1],yVr[r][1],y1v.y)
        #undef EC
      }
      gs_publish(ss, RED, rno);

      // ---- speculative interp coefficients (u only) into P[pp^1] ----
      {
        float* Pn = Pb0 + (pp^1)*PH;
        #pragma unroll
        for (int r = 0; r < 4; r++) {
          float2 k2u = *(const float2*)(KS2 + (r0+r)*HID + c0);
          float2 k3u = *(const float2*)(KS3 + (r0+r)*HID + c0);
          float2 k4u = *(const float2*)(KS4 + (r0+r)*HID + c0);
          float2 k5u = *(const float2*)(KS5 + (r0+r)*HID + c0);
          float2 y1u = *(const float2*)(yalt + (r0+r)*HID + c0);
          float2 A2f, B2f, C2f, D2f, E2f;
          #define IC(W, K0,K2,K3,K4,K5,K6,Y0,Y1) { \
            float ym = fmaf(dt, CM0*(K0) + CM2*(K2) + CM3*(K3) + CM4*(K4) + CM5*(K5) + CM6*(K6), (Y0)); \
            float D0 = dt*(K0), D1 = dt*(K6); \
            A2f.W = -2.f*D0 + 2.f*D1 -  8.f*(Y0) -  8.f*(Y1) + 16.f*ym; \
            B2f.W =  5.f*D0 - 3.f*D1 + 18.f*(Y0) + 14.f*(Y1) - 32.f*ym; \
            C2f.W = -4.f*D0 +     D1 - 11.f*(Y0) -  5.f*(Y1) + 16.f*ym; \
            D2f.W = D0; E2f.W = (Y0); }
          IC(x, kU0[r][0],k2u.x,k3u.x,k4u.x,k5u.x,kU6[r][0],yUr[r][0],y1u.x)
          IC(y, kU0[r][1],k2u.y,k3u.y,k4u.y,k5u.y,kU6[r][1],yUr[r][1],y1u.y)
          #undef IC
          *(float2*)(Pn + 0*ARR + (r0+r)*HID + c0) = A2f;
          *(float2*)(Pn + 1*ARR + (r0+r)*HID + c0) = B2f;
          *(float2*)(Pn + 2*ARR + (r0+r)*HID + c0) = C2f;
          *(float2*)(Pn + 3*ARR + (r0+r)*HID + c0) = D2f;
          *(float2*)(Pn + 4*ARR + (r0+r)*HID + c0) = E2f;
        }
      }

      float tss = gs_gather(RED, rno); rno++;
      float ratio  = sqrtf(tss * (1.f/524288.f));
      float er     = fmaxf(ratio, 1e-10f);
      float dfac   = (ratio < 1.f) ? 1.f : 0.2f;
      float factor = fminf(10.f, fmaxf(0.9f*powf(er, -0.2f), dfac));
      bool  accept = (ratio <= 1.f);

      if (accept) {
        pp ^= 1;                         // speculative P becomes valid
        // FSAL: k0 <- k6 (register copies)
        #pragma unroll
        for (int r = 0; r < 4; r++) {
          kU0[r][0] = kU6[r][0]; kU0[r][1] = kU6[r][1];
          kV0[r][0] = kV6[r][0]; kV0[r][1] = kV6[r][1];
        }
        // y-regs <- y1 (thread-own reload)
        #pragma unroll
        for (int r = 0; r < 4; r++) {
          float2 yu = *(const float2*)(yalt + (r0+r)*HID + c0);
          float2 yv = *(const float2*)(yalt + ARR + (r0+r)*HID + c0);
          yUr[r][0] = yu.x; yUr[r][1] = yu.y;
          yVr[r][0] = yv.x; yVr[r][1] = yv.y;
        }
        last_t = t; t = t + dt; p ^= 1;
      }
      // reject: k0/y regs intact; nothing to restore
      dt = dt * factor;
      __syncthreads();   // protect y buffers / P before next iteration
    }

    // evaluate interpolation polynomial at the target and store
    float xr = (tf - last_t) / (t - last_t);
    const float* Pc = Pb0 + pp*PH;
    #pragma unroll
    for (int q = 0; q < 2; q++) {
      int e4 = tid + q*256;
      float4 A4 = ((const float4*)Pc)[e4];
      float4 B4 = ((const float4*)(Pc +   ARR))[e4];
      float4 C4 = ((const float4*)(Pc + 2*ARR))[e4];
      float4 D4 = ((const float4*)(Pc + 3*ARR))[e4];
      float4 E4 = ((const float4*)(Pc + 4*ARR))[e4];
      float4 o;
      o.x = fmaf(fmaf(fmaf(fmaf(A4.x, xr, B4.x), xr, C4.x), xr, D4.x), xr, E4.x);
      o.y = fmaf(fmaf(fmaf(fmaf(A4.y, xr, B4.y), xr, C4.y), xr, D4.y), xr, E4.y);
      o.z = fmaf(fmaf(fmaf(fmaf(A4.z, xr, B4.z), xr, C4.z), xr, D4.z), xr, E4.z);
      o.w = fmaf(fmaf(fmaf(fmaf(A4.w, xr, B4.w), xr, C4.w), xr, D4.w), xr, E4.w);
      int e = e4*4; int r = e >> 6; int h = e & 63;
      *(float4*)(out + ((size_t)(brow + r)*FORECAST + (tgt - 1))*HID + h) = o;
    }
  }
}

extern "C" void kernel_launch(void* const* d_in, const int* in_sizes, int n_in,
                              void* d_out, int out_size) {
  (void)in_sizes; (void)n_in; (void)out_size;
  const float* x   = (const float*)d_in[0];
  const float* tri = (const float*)d_in[1];
  float* out = (float*)d_out;
  cudaFuncSetAttribute(sindy_kernel,
                       cudaFuncAttributeMaxDynamicSharedMemorySize, SMEM_BYTES);
  reset_kernel<<<1, 128>>>();
  sindy_kernel<<<NBLK, NTH, SMEM_BYTES>>>(x, tri, out);
}